// round 1
// baseline (speedup 1.0000x reference)
#include <cuda_runtime.h>

#define N_NODES 100000
#define HDIM 128
#define H2DIM 256
#define N_EDGES 600000
#define NSUB 20000
#define ESUB 200000
#define NLAYERS 3
#define NSUBT 2
#define OUTDIM 128

// ---------------- persistent scratch (static device globals; no allocs) ----
__device__ float g_x   [N_NODES * HDIM];
__device__ float g_agg [N_NODES * HDIM];
__device__ float g_h   [N_NODES * H2DIM];
__device__ float g_msg [N_NODES * HDIM];
__device__ float g_sx  [NSUB * HDIM];
__device__ float g_sxh [NSUB * H2DIM];
__device__ float g_sx2 [NSUB * HDIM];
__device__ float g_sum  [H2DIM];
__device__ float g_sumsq[H2DIM];
__device__ float g_scale[H2DIM];
__device__ float g_shift[H2DIM];

// ---------------- small utility kernels ------------------------------------
__global__ void k_copy4(float* __restrict__ dst, const float* __restrict__ src, int n4) {
    int i = blockIdx.x * blockDim.x + threadIdx.x;
    if (i < n4) reinterpret_cast<float4*>(dst)[i] = reinterpret_cast<const float4*>(src)[i];
}

__global__ void k_zero4(float* __restrict__ dst, int n4) {
    int i = blockIdx.x * blockDim.x + threadIdx.x;
    if (i < n4) reinterpret_cast<float4*>(dst)[i] = make_float4(0.f, 0.f, 0.f, 0.f);
}

// agg = (1 + eps[layer]) * x
__global__ void k_init_agg(float* __restrict__ agg, const float* __restrict__ x,
                           const float* __restrict__ eps, int layer, int n4) {
    int i = blockIdx.x * blockDim.x + threadIdx.x;
    if (i >= n4) return;
    float e = 1.0f + __ldg(eps + layer);
    float4 v = reinterpret_cast<const float4*>(x)[i];
    v.x *= e; v.y *= e; v.z *= e; v.w *= e;
    reinterpret_cast<float4*>(agg)[i] = v;
}

// out[didx[e]] += in[sidx[e]]  (H=128 floats per row; one warp per edge)
__global__ void k_scatter(float* __restrict__ out, const float* __restrict__ in,
                          const int* __restrict__ sidx, const int* __restrict__ didx, int nE) {
    int w = (blockIdx.x * blockDim.x + threadIdx.x) >> 5;
    if (w >= nE) return;
    int lane = threadIdx.x & 31;
    int s = __ldg(sidx + w);
    int d = __ldg(didx + w);
    const float* ip = in + (size_t)s * HDIM + lane;
    float* op = out + (size_t)d * HDIM + lane;
#pragma unroll
    for (int j = 0; j < 4; j++)
        atomicAdd(op + 32 * j, __ldg(ip + 32 * j));
}

__global__ void k_zero_stats() {
    g_sum[threadIdx.x] = 0.f;
    g_sumsq[threadIdx.x] = 0.f;
}

// per-column sum / sumsq of h[M, 256]
__global__ void k_colstats(const float* __restrict__ h, int M) {
    int c = threadIdx.x;  // 256 threads
    float s = 0.f, ss = 0.f;
    for (int r = blockIdx.x; r < M; r += gridDim.x) {
        float v = h[(size_t)r * H2DIM + c];
        s += v; ss += v * v;
    }
    atomicAdd(&g_sum[c], s);
    atomicAdd(&g_sumsq[c], ss);
}

// scale/shift for affine BN:  bn(h) = h*scale + shift
__global__ void k_bnfin(const float* __restrict__ gamma, const float* __restrict__ beta,
                        float invM) {
    int c = threadIdx.x;  // 256 threads
    float mean = g_sum[c] * invM;
    float var  = g_sumsq[c] * invM - mean * mean;
    float sc   = __ldg(gamma + c) * rsqrtf(var + 1e-5f);
    g_scale[c] = sc;
    g_shift[c] = __ldg(beta + c) - mean * sc;
}

// ---------------- SGEMM: C[M,Nw] = op(A[M,K]) @ B[K,Nw] (+bias, +epilogue) --
// AOP: 0 = identity A, 1 = relu(A*scale[k] + shift[k])  (fused BN+ReLU)
// EOP: 0 = +bias ; 1 = relu(+bias) ; 2 = C += (acc + bias)  (residual accum)
// Block tile 128x128, BK=8, 256 threads, 8x8 per-thread micro-tile.
template <int AOP, int EOP>
__global__ __launch_bounds__(256, 2) void k_sgemm(
    const float* __restrict__ A, const float* __restrict__ B,
    const float* __restrict__ bias, float* __restrict__ C,
    int M, int K, int Nw,
    const float* __restrict__ scale, const float* __restrict__ shift) {
    __shared__ float As[8][128];
    __shared__ float Bs[8][128];

    const int tid = threadIdx.x;
    const int tx = tid & 15;
    const int ty = tid >> 4;
    const int row0 = blockIdx.y * 128;
    const int col0 = blockIdx.x * 128;

    // A tile load map: 128 rows x 8 cols, one float4 per thread
    const int a_row = tid >> 1;
    const int a_col = (tid & 1) * 4;
    // B tile load map: 8 rows x 128 cols
    const int b_row = tid >> 5;
    const int b_col = (tid & 31) * 4;

    const bool a_ok = (row0 + a_row) < M;
    const float* Abase = A + (size_t)(row0 + a_row) * K + a_col;
    const float* Bbase = B + (size_t)b_row * Nw + col0 + b_col;

    float acc[8][8];
#pragma unroll
    for (int i = 0; i < 8; i++)
#pragma unroll
        for (int j = 0; j < 8; j++) acc[i][j] = 0.f;

    auto fetchA = [&](int t) -> float4 {
        float4 v = make_float4(0.f, 0.f, 0.f, 0.f);
        if (a_ok) {
            v = *reinterpret_cast<const float4*>(Abase + t * 8);
            if (AOP == 1) {
                int gk = t * 8 + a_col;
                float4 sc = *reinterpret_cast<const float4*>(scale + gk);
                float4 sh = *reinterpret_cast<const float4*>(shift + gk);
                v.x = fmaxf(fmaf(v.x, sc.x, sh.x), 0.f);
                v.y = fmaxf(fmaf(v.y, sc.y, sh.y), 0.f);
                v.z = fmaxf(fmaf(v.z, sc.z, sh.z), 0.f);
                v.w = fmaxf(fmaf(v.w, sc.w, sh.w), 0.f);
            }
        }
        return v;
    };
    auto fetchB = [&](int t) -> float4 {
        return *reinterpret_cast<const float4*>(Bbase + (size_t)t * 8 * Nw);
    };
    auto storeA = [&](float4 v) {
        As[a_col + 0][a_row] = v.x;
        As[a_col + 1][a_row] = v.y;
        As[a_col + 2][a_row] = v.z;
        As[a_col + 3][a_row] = v.w;
    };
    auto storeB = [&](float4 v) {
        *reinterpret_cast<float4*>(&Bs[b_row][b_col]) = v;
    };

    storeA(fetchA(0));
    storeB(fetchB(0));
    __syncthreads();

    const int nT = K >> 3;
    for (int t = 0; t < nT; t++) {
        float4 aN, bN;
        if (t + 1 < nT) { aN = fetchA(t + 1); bN = fetchB(t + 1); }
#pragma unroll
        for (int k = 0; k < 8; k++) {
            float a[8], b[8];
            *reinterpret_cast<float4*>(a)     = *reinterpret_cast<const float4*>(&As[k][ty * 4]);
            *reinterpret_cast<float4*>(a + 4) = *reinterpret_cast<const float4*>(&As[k][64 + ty * 4]);
            *reinterpret_cast<float4*>(b)     = *reinterpret_cast<const float4*>(&Bs[k][tx * 4]);
            *reinterpret_cast<float4*>(b + 4) = *reinterpret_cast<const float4*>(&Bs[k][64 + tx * 4]);
#pragma unroll
            for (int i = 0; i < 8; i++)
#pragma unroll
                for (int j = 0; j < 8; j++)
                    acc[i][j] = fmaf(a[i], b[j], acc[i][j]);
        }
        __syncthreads();
        if (t + 1 < nT) {
            storeA(aN);
            storeB(bN);
            __syncthreads();
        }
    }

    // epilogue
    float4 bi0 = *reinterpret_cast<const float4*>(bias + col0 + tx * 4);
    float4 bi1 = *reinterpret_cast<const float4*>(bias + col0 + 64 + tx * 4);
#pragma unroll
    for (int i = 0; i < 8; i++) {
        int r = row0 + ((i < 4) ? (ty * 4 + i) : (64 + ty * 4 + (i - 4)));
        if (r >= M) continue;
        float* crow = C + (size_t)r * Nw + col0;
        float4 v0 = make_float4(acc[i][0] + bi0.x, acc[i][1] + bi0.y,
                                acc[i][2] + bi0.z, acc[i][3] + bi0.w);
        float4 v1 = make_float4(acc[i][4] + bi1.x, acc[i][5] + bi1.y,
                                acc[i][6] + bi1.z, acc[i][7] + bi1.w);
        if (EOP == 1) {
            v0.x = fmaxf(v0.x, 0.f); v0.y = fmaxf(v0.y, 0.f);
            v0.z = fmaxf(v0.z, 0.f); v0.w = fmaxf(v0.w, 0.f);
            v1.x = fmaxf(v1.x, 0.f); v1.y = fmaxf(v1.y, 0.f);
            v1.z = fmaxf(v1.z, 0.f); v1.w = fmaxf(v1.w, 0.f);
        }
        if (EOP == 2) {
            float4 o0 = *reinterpret_cast<const float4*>(crow + tx * 4);
            float4 o1 = *reinterpret_cast<const float4*>(crow + 64 + tx * 4);
            v0.x += o0.x; v0.y += o0.y; v0.z += o0.z; v0.w += o0.w;
            v1.x += o1.x; v1.y += o1.y; v1.z += o1.z; v1.w += o1.w;
        }
        *reinterpret_cast<float4*>(crow + tx * 4) = v0;
        *reinterpret_cast<float4*>(crow + 64 + tx * 4) = v1;
    }
}

// ---------------- host orchestration ---------------------------------------
static inline int blk4(int n) { return (n / 4 + 255) / 256; }

extern "C" void kernel_launch(void* const* d_in, const int* in_sizes, int n_in,
                              void* d_out, int out_size) {
    const float* x_in    = (const float*)d_in[0];
    const int*   edge    = (const int*)d_in[1];   // [2, E]: src then dst
    const int*   se0     = (const int*)d_in[2];   // [2, ESUB]: row then col
    const int*   se1     = (const int*)d_in[3];
    const float* msg_w1  = (const float*)d_in[4];
    const float* msg_b1  = (const float*)d_in[5];
    const float* bn_g    = (const float*)d_in[6];
    const float* bn_b    = (const float*)d_in[7];
    const float* msg_w2  = (const float*)d_in[8];
    const float* msg_b2  = (const float*)d_in[9];
    const float* eps_gin = (const float*)d_in[10];
    const float* n2s_w1  = (const float*)d_in[11];
    const float* n2s_b1  = (const float*)d_in[12];
    const float* n2s_w2  = (const float*)d_in[13];
    const float* n2s_b2  = (const float*)d_in[14];
    const float* s2n_w1  = (const float*)d_in[15];
    const float* s2n_b1  = (const float*)d_in[16];
    const float* s2n_w2  = (const float*)d_in[17];
    const float* s2n_b2  = (const float*)d_in[18];
    const float* out_w1  = (const float*)d_in[19];
    const float* out_b1  = (const float*)d_in[20];
    const float* out_w2  = (const float*)d_in[21];
    const float* out_b2  = (const float*)d_in[22];

    float *xb, *aggb, *hb, *msgb, *sxb, *sxhb, *sx2b, *scaleb, *shiftb;
    cudaGetSymbolAddress((void**)&xb,    g_x);
    cudaGetSymbolAddress((void**)&aggb,  g_agg);
    cudaGetSymbolAddress((void**)&hb,    g_h);
    cudaGetSymbolAddress((void**)&msgb,  g_msg);
    cudaGetSymbolAddress((void**)&sxb,   g_sx);
    cudaGetSymbolAddress((void**)&sxhb,  g_sxh);
    cudaGetSymbolAddress((void**)&sx2b,  g_sx2);
    cudaGetSymbolAddress((void**)&scaleb, g_scale);
    cudaGetSymbolAddress((void**)&shiftb, g_shift);

    const int nh4  = N_NODES * HDIM / 4;
    const int sx4  = NSUB * HDIM / 4;

    dim3 gN2(2, (N_NODES + 127) / 128);  // [N,*] -> 256 cols
    dim3 gN1(1, (N_NODES + 127) / 128);  // [N,*] -> 128 cols
    dim3 gS2(2, (NSUB + 127) / 128);
    dim3 gS1(1, (NSUB + 127) / 128);

    const int scatterBlocksE = (N_EDGES * 32 + 255) / 256;
    const int scatterBlocksS = (ESUB * 32 + 255) / 256;

    // x <- input
    k_copy4<<<blk4(N_NODES * HDIM), 256>>>(xb, x_in, nh4);

    for (int i = 0; i < NLAYERS; i++) {
        // ---- GIN aggregation: agg = (1+eps)x ; agg[dst] += x[src] ----
        k_init_agg<<<blk4(N_NODES * HDIM), 256>>>(aggb, xb, eps_gin, i, nh4);
        k_scatter<<<scatterBlocksE, 256>>>(aggb, xb, edge, edge + N_EDGES, N_EDGES);

        // ---- h = agg @ msg_w1 + b1 ----
        k_sgemm<0, 0><<<gN2, 256>>>(aggb, msg_w1 + (size_t)i * HDIM * H2DIM,
                                    msg_b1 + (size_t)i * H2DIM, hb,
                                    N_NODES, HDIM, H2DIM, nullptr, nullptr);
        // ---- BN stats ----
        k_zero_stats<<<1, 256>>>();
        k_colstats<<<2048, 256>>>(hb, N_NODES);
        k_bnfin<<<1, 256>>>(bn_g + (size_t)i * H2DIM, bn_b + (size_t)i * H2DIM,
                            1.0f / (float)N_NODES);
        // ---- x = relu(bn(h)) @ msg_w2 + b2  (BN+ReLU fused on A-read) ----
        k_sgemm<1, 0><<<gN1, 256>>>(hb, msg_w2 + (size_t)i * H2DIM * HDIM,
                                    msg_b2 + (size_t)i * HDIM, xb,
                                    N_NODES, H2DIM, HDIM, scaleb, shiftb);

        // ---- substructure message passing ----
        for (int s = 0; s < NSUBT; s++) {
            const int* se = (s == 0) ? se0 : se1;   // row = se, col = se + ESUB
            const size_t widx = (size_t)i * NSUBT + s;

            // sx[col] += x[row]
            k_zero4<<<blk4(NSUB * HDIM), 256>>>(sxb, sx4);
            k_scatter<<<scatterBlocksS, 256>>>(sxb, xb, se, se + ESUB, ESUB);

            // sx2 = mlp_n2s(sx)
            k_sgemm<0, 1><<<gS2, 256>>>(sxb, n2s_w1 + widx * HDIM * H2DIM,
                                        n2s_b1 + widx * H2DIM, sxhb,
                                        NSUB, HDIM, H2DIM, nullptr, nullptr);
            k_sgemm<0, 0><<<gS1, 256>>>(sxhb, n2s_w2 + widx * H2DIM * HDIM,
                                        n2s_b2 + widx * HDIM, sx2b,
                                        NSUB, H2DIM, HDIM, nullptr, nullptr);

            // msg[row] += sx2[col]
            k_zero4<<<blk4(N_NODES * HDIM), 256>>>(msgb, nh4);
            k_scatter<<<scatterBlocksS, 256>>>(msgb, sx2b, se + ESUB, se, ESUB);

            // x += mlp_s2n(msg)
            k_sgemm<0, 1><<<gN2, 256>>>(msgb, s2n_w1 + widx * HDIM * H2DIM,
                                        s2n_b1 + widx * H2DIM, hb,
                                        N_NODES, HDIM, H2DIM, nullptr, nullptr);
            k_sgemm<0, 2><<<gN1, 256>>>(hb, s2n_w2 + widx * H2DIM * HDIM,
                                        s2n_b2 + widx * HDIM, xb,
                                        N_NODES, H2DIM, HDIM, nullptr, nullptr);
        }
    }

    // ---- output head ----
    k_sgemm<0, 1><<<gN2, 256>>>(xb, out_w1, out_b1, hb,
                                N_NODES, HDIM, H2DIM, nullptr, nullptr);
    k_sgemm<0, 0><<<gN1, 256>>>(hb, out_w2, out_b2, (float*)d_out,
                                N_NODES, H2DIM, OUTDIM, nullptr, nullptr);
}

// round 3
// speedup vs baseline: 1.4041x; 1.4041x over previous
#include <cuda_runtime.h>
#include <cuda_bf16.h>
#include <cstdint>

#define N_NODES 100000
#define HDIM 128
#define H2DIM 256
#define N_EDGES 600000
#define NSUB 20000
#define ESUB 200000
#define NLAYERS 3
#define NSUBT 2
#define OUTDIM 128

// ---------------- persistent scratch (static device globals; no allocs) ----
__device__ float g_x   [N_NODES * HDIM];
__device__ float g_agg [N_NODES * HDIM];
__device__ float g_h   [N_NODES * H2DIM];
__device__ float g_msg [N_NODES * HDIM];
__device__ float g_sx  [NSUB * HDIM];
__device__ float g_sxh [NSUB * H2DIM];
__device__ float g_sx2 [NSUB * HDIM];
__device__ float g_sum  [H2DIM];
__device__ float g_sumsq[H2DIM];
__device__ float g_scale[H2DIM];
__device__ float g_shift[H2DIM];
// split/transposed weights: [n,k] bf16, hi and lo parts
#define W_TOTAL 1048576
__device__ __nv_bfloat16 g_whi[W_TOTAL];
__device__ __nv_bfloat16 g_wlo[W_TOTAL];

// ---------------- small utility kernels ------------------------------------
__global__ void k_copy4(float* __restrict__ dst, const float* __restrict__ src, int n4) {
    int i = blockIdx.x * blockDim.x + threadIdx.x;
    if (i < n4) reinterpret_cast<float4*>(dst)[i] = reinterpret_cast<const float4*>(src)[i];
}
__global__ void k_zero4(float* __restrict__ dst, int n4) {
    int i = blockIdx.x * blockDim.x + threadIdx.x;
    if (i < n4) reinterpret_cast<float4*>(dst)[i] = make_float4(0.f, 0.f, 0.f, 0.f);
}
__global__ void k_init_agg(float* __restrict__ agg, const float* __restrict__ x,
                           const float* __restrict__ eps, int layer, int n4) {
    int i = blockIdx.x * blockDim.x + threadIdx.x;
    if (i >= n4) return;
    float e = 1.0f + __ldg(eps + layer);
    float4 v = reinterpret_cast<const float4*>(x)[i];
    v.x *= e; v.y *= e; v.z *= e; v.w *= e;
    reinterpret_cast<float4*>(agg)[i] = v;
}
__global__ void k_scatter(float* __restrict__ out, const float* __restrict__ in,
                          const int* __restrict__ sidx, const int* __restrict__ didx, int nE) {
    int w = (blockIdx.x * blockDim.x + threadIdx.x) >> 5;
    if (w >= nE) return;
    int lane = threadIdx.x & 31;
    int s = __ldg(sidx + w);
    int d = __ldg(didx + w);
    const float* ip = in + (size_t)s * HDIM + lane;
    float* op = out + (size_t)d * HDIM + lane;
#pragma unroll
    for (int j = 0; j < 4; j++)
        atomicAdd(op + 32 * j, __ldg(ip + 32 * j));
}
__global__ void k_zero_stats() {
    g_sum[threadIdx.x] = 0.f;
    g_sumsq[threadIdx.x] = 0.f;
}
__global__ void k_colstats(const float* __restrict__ h, int M) {
    int c = threadIdx.x;
    float s = 0.f, ss = 0.f;
    for (int r = blockIdx.x; r < M; r += gridDim.x) {
        float v = h[(size_t)r * H2DIM + c];
        s += v; ss += v * v;
    }
    atomicAdd(&g_sum[c], s);
    atomicAdd(&g_sumsq[c], ss);
}
__global__ void k_bnfin(const float* __restrict__ gamma, const float* __restrict__ beta,
                        float invM) {
    int c = threadIdx.x;
    float mean = g_sum[c] * invM;
    float var  = g_sumsq[c] * invM - mean * mean;
    float sc   = __ldg(gamma + c) * rsqrtf(var + 1e-5f);
    g_scale[c] = sc;
    g_shift[c] = __ldg(beta + c) - mean * sc;
}
// split fp32 weight [cnt][K,Nw] -> transposed bf16 hi/lo [cnt][Nw,K]
__global__ void k_prep(const float* __restrict__ W, int K, int Nw, int cnt,
                       __nv_bfloat16* __restrict__ hi, __nv_bfloat16* __restrict__ lo) {
    int i = blockIdx.x * blockDim.x + threadIdx.x;
    int per = K * Nw;
    if (i >= cnt * per) return;
    int m = i / per, r = i % per;
    int k = r / Nw, n = r % Nw;
    float w = W[i];
    __nv_bfloat16 h = __float2bfloat16(w);
    float res = w - __bfloat162float(h);
    size_t o = (size_t)m * per + (size_t)n * K + k;
    hi[o] = h;
    lo[o] = __float2bfloat16(res);
}

// ---------------- mma.sync helpers ------------------------------------------
__device__ __forceinline__ uint32_t smem_u32(const void* p) {
    uint32_t a;
    asm("{ .reg .u64 t; cvta.to.shared.u64 t, %1; cvt.u32.u64 %0, t; }" : "=r"(a) : "l"(p));
    return a;
}
__device__ __forceinline__ void ldsm_x4(uint32_t* r, uint32_t addr) {
    asm volatile("ldmatrix.sync.aligned.m8n8.x4.shared.b16 {%0,%1,%2,%3}, [%4];"
                 : "=r"(r[0]), "=r"(r[1]), "=r"(r[2]), "=r"(r[3]) : "r"(addr));
}
__device__ __forceinline__ void mma16816(float* d, const uint32_t* a, uint32_t b0, uint32_t b1) {
    asm volatile(
        "mma.sync.aligned.m16n8k16.row.col.f32.bf16.bf16.f32 "
        "{%0,%1,%2,%3}, {%4,%5,%6,%7}, {%8,%9}, {%0,%1,%2,%3};"
        : "+f"(d[0]), "+f"(d[1]), "+f"(d[2]), "+f"(d[3])
        : "r"(a[0]), "r"(a[1]), "r"(a[2]), "r"(a[3]), "r"(b0), "r"(b1));
}

// ---------------- mma.sync split-bf16 GEMM ----------------------------------
// C[M,Nw] = op(A[M,K]) @ B[K,Nw] (+bias, epilogue), D += Ahi*Bhi + Alo*Bhi + Ahi*Blo
// AOP: 0 identity, 1 relu(A*scale[k]+shift[k]) fused BN
// EOP: 0 +bias ; 1 relu(+bias) ; 2 C += acc+bias (residual)
// 128x128 CTA tile, 8 warps (4M x 2N), warp tile 32x64, KB=128 chunks.
// SMEM tiles 128x128 bf16, row stride 256B, 16B-chunk swizzle: c16 ^= (row&7).
#define S_AHI 0
#define S_ALO 32768
#define S_BHI 65536
#define S_BLO 98304
#define GEMM_SMEM 131072

template <int AOP, int EOP>
__global__ __launch_bounds__(256, 1) void k_gemm_mma(
    const float* __restrict__ A, const __nv_bfloat16* __restrict__ Bhi,
    const __nv_bfloat16* __restrict__ Blo, const float* __restrict__ bias,
    float* __restrict__ C, int M, int K, int Nw,
    const float* __restrict__ scale, const float* __restrict__ shift) {
    extern __shared__ char smem[];
    const uint32_t sbase = smem_u32(smem);
    const int tid = threadIdx.x;
    const int wid = tid >> 5;
    const int lane = tid & 31;
    const int row0 = blockIdx.y * 128;
    const int col0 = blockIdx.x * 128;
    const int wm = (wid & 3) * 32;   // warp M offset in tile
    const int wn = (wid >> 2) * 64;  // warp N offset in tile

    float acc[2][8][4];
#pragma unroll
    for (int i = 0; i < 2; i++)
#pragma unroll
        for (int j = 0; j < 8; j++)
#pragma unroll
            for (int q = 0; q < 4; q++) acc[i][j][q] = 0.f;

    for (int chunk = 0; chunk < K; chunk += 128) {
        // ---- fill SMEM: 2048 16B-chunk tasks over 256 threads (8 iters) ----
#pragma unroll
        for (int it = 0; it < 8; it++) {
            int task = tid + it * 256;
            int r = task >> 4;          // tile row (A) / tile n (B)
            int c16 = task & 15;        // 16B chunk within row (8 elems)
            uint32_t soff = (uint32_t)r * 256u + (uint32_t)((c16 ^ (r & 7)) << 4);
            // A: read 8 fp32, convert hi/lo
            float4 v0 = make_float4(0.f, 0.f, 0.f, 0.f), v1 = v0;
            if (row0 + r < M) {
                const float* ap = A + (size_t)(row0 + r) * K + chunk + c16 * 8;
                v0 = *reinterpret_cast<const float4*>(ap);
                v1 = *reinterpret_cast<const float4*>(ap + 4);
                if (AOP == 1) {
                    int gk = chunk + c16 * 8;
                    float4 sc0 = *reinterpret_cast<const float4*>(scale + gk);
                    float4 sc1 = *reinterpret_cast<const float4*>(scale + gk + 4);
                    float4 sh0 = *reinterpret_cast<const float4*>(shift + gk);
                    float4 sh1 = *reinterpret_cast<const float4*>(shift + gk + 4);
                    v0.x = fmaxf(fmaf(v0.x, sc0.x, sh0.x), 0.f);
                    v0.y = fmaxf(fmaf(v0.y, sc0.y, sh0.y), 0.f);
                    v0.z = fmaxf(fmaf(v0.z, sc0.z, sh0.z), 0.f);
                    v0.w = fmaxf(fmaf(v0.w, sc0.w, sh0.w), 0.f);
                    v1.x = fmaxf(fmaf(v1.x, sc1.x, sh1.x), 0.f);
                    v1.y = fmaxf(fmaf(v1.y, sc1.y, sh1.y), 0.f);
                    v1.z = fmaxf(fmaf(v1.z, sc1.z, sh1.z), 0.f);
                    v1.w = fmaxf(fmaf(v1.w, sc1.w, sh1.w), 0.f);
                }
            }
            __nv_bfloat162 h01 = __float22bfloat162_rn(make_float2(v0.x, v0.y));
            __nv_bfloat162 h23 = __float22bfloat162_rn(make_float2(v0.z, v0.w));
            __nv_bfloat162 h45 = __float22bfloat162_rn(make_float2(v1.x, v1.y));
            __nv_bfloat162 h67 = __float22bfloat162_rn(make_float2(v1.z, v1.w));
            float2 f01 = __bfloat1622float2(h01), f23 = __bfloat1622float2(h23);
            float2 f45 = __bfloat1622float2(h45), f67 = __bfloat1622float2(h67);
            __nv_bfloat162 l01 = __float22bfloat162_rn(make_float2(v0.x - f01.x, v0.y - f01.y));
            __nv_bfloat162 l23 = __float22bfloat162_rn(make_float2(v0.z - f23.x, v0.w - f23.y));
            __nv_bfloat162 l45 = __float22bfloat162_rn(make_float2(v1.x - f45.x, v1.y - f45.y));
            __nv_bfloat162 l67 = __float22bfloat162_rn(make_float2(v1.z - f67.x, v1.w - f67.y));
            uint4 hp, lp;
            hp.x = *(uint32_t*)&h01; hp.y = *(uint32_t*)&h23;
            hp.z = *(uint32_t*)&h45; hp.w = *(uint32_t*)&h67;
            lp.x = *(uint32_t*)&l01; lp.y = *(uint32_t*)&l23;
            lp.z = *(uint32_t*)&l45; lp.w = *(uint32_t*)&l67;
            *reinterpret_cast<uint4*>(smem + S_AHI + soff) = hp;
            *reinterpret_cast<uint4*>(smem + S_ALO + soff) = lp;
            // B: pre-split bf16 [Nw,K]
            const __nv_bfloat16* bh = Bhi + (size_t)(col0 + r) * K + chunk + c16 * 8;
            const __nv_bfloat16* bl = Blo + (size_t)(col0 + r) * K + chunk + c16 * 8;
            *reinterpret_cast<uint4*>(smem + S_BHI + soff) = *reinterpret_cast<const uint4*>(bh);
            *reinterpret_cast<uint4*>(smem + S_BLO + soff) = *reinterpret_cast<const uint4*>(bl);
        }
        __syncthreads();

        // ---- compute: 8 ksteps of 16 ----
#pragma unroll
        for (int ks = 0; ks < 8; ks++) {
            uint32_t ahi[2][4], alo[2][4];
#pragma unroll
            for (int ms = 0; ms < 2; ms++) {
                int r = wm + ms * 16 + (lane & 15);
                int c16 = ks * 2 + (lane >> 4);
                uint32_t off = (uint32_t)r * 256u + (uint32_t)(((c16 ^ (r & 7))) << 4);
                ldsm_x4(ahi[ms], sbase + S_AHI + off);
                ldsm_x4(alo[ms], sbase + S_ALO + off);
            }
#pragma unroll
            for (int p = 0; p < 4; p++) {  // n-tile pairs: 16 n each
                int n = wn + p * 16 + ((lane >> 4) << 3) + (lane & 7);
                int c16 = ks * 2 + ((lane >> 3) & 1);
                uint32_t off = (uint32_t)n * 256u + (uint32_t)(((c16 ^ (n & 7))) << 4);
                uint32_t bh[4], bl[4];
                ldsm_x4(bh, sbase + S_BHI + off);
                ldsm_x4(bl, sbase + S_BLO + off);
#pragma unroll
                for (int ms = 0; ms < 2; ms++) {
                    mma16816(acc[ms][2 * p],     ahi[ms], bh[0], bh[1]);
                    mma16816(acc[ms][2 * p + 1], ahi[ms], bh[2], bh[3]);
                    mma16816(acc[ms][2 * p],     alo[ms], bh[0], bh[1]);
                    mma16816(acc[ms][2 * p + 1], alo[ms], bh[2], bh[3]);
                    mma16816(acc[ms][2 * p],     ahi[ms], bl[0], bl[1]);
                    mma16816(acc[ms][2 * p + 1], ahi[ms], bl[2], bl[3]);
                }
            }
        }
        __syncthreads();
    }

    // ---- epilogue: register fragments -> C ----
#pragma unroll
    for (int ms = 0; ms < 2; ms++) {
#pragma unroll
        for (int nt = 0; nt < 8; nt++) {
            int c = col0 + wn + nt * 8 + (lane & 3) * 2;
            float2 bi = *reinterpret_cast<const float2*>(bias + c);
            int r = row0 + wm + ms * 16 + (lane >> 2);
#pragma unroll
            for (int half = 0; half < 2; half++) {
                int rr = r + half * 8;
                if (rr >= M) continue;
                float2 v;
                v.x = acc[ms][nt][2 * half + 0] + bi.x;
                v.y = acc[ms][nt][2 * half + 1] + bi.y;
                if (EOP == 1) { v.x = fmaxf(v.x, 0.f); v.y = fmaxf(v.y, 0.f); }
                float* cp = C + (size_t)rr * Nw + c;
                if (EOP == 2) {
                    float2 o = *reinterpret_cast<const float2*>(cp);
                    v.x += o.x; v.y += o.y;
                }
                *reinterpret_cast<float2*>(cp) = v;
            }
        }
    }
}

// ---------------- host orchestration ---------------------------------------
static inline int blk4(int n) { return (n / 4 + 255) / 256; }

extern "C" void kernel_launch(void* const* d_in, const int* in_sizes, int n_in,
                              void* d_out, int out_size) {
    const float* x_in    = (const float*)d_in[0];
    const int*   edge    = (const int*)d_in[1];
    const int*   se0     = (const int*)d_in[2];
    const int*   se1     = (const int*)d_in[3];
    const float* msg_w1  = (const float*)d_in[4];
    const float* msg_b1  = (const float*)d_in[5];
    const float* bn_g    = (const float*)d_in[6];
    const float* bn_b    = (const float*)d_in[7];
    const float* msg_w2  = (const float*)d_in[8];
    const float* msg_b2  = (const float*)d_in[9];
    const float* eps_gin = (const float*)d_in[10];
    const float* n2s_w1  = (const float*)d_in[11];
    const float* n2s_b1  = (const float*)d_in[12];
    const float* n2s_w2  = (const float*)d_in[13];
    const float* n2s_b2  = (const float*)d_in[14];
    const float* s2n_w1  = (const float*)d_in[15];
    const float* s2n_b1  = (const float*)d_in[16];
    const float* s2n_w2  = (const float*)d_in[17];
    const float* s2n_b2  = (const float*)d_in[18];
    const float* out_w1  = (const float*)d_in[19];
    const float* out_b1  = (const float*)d_in[20];
    const float* out_w2  = (const float*)d_in[21];
    const float* out_b2  = (const float*)d_in[22];

    float *xb, *aggb, *hb, *msgb, *sxb, *sxhb, *sx2b, *scaleb, *shiftb;
    __nv_bfloat16 *whi, *wlo;
    cudaGetSymbolAddress((void**)&xb,    g_x);
    cudaGetSymbolAddress((void**)&aggb,  g_agg);
    cudaGetSymbolAddress((void**)&hb,    g_h);
    cudaGetSymbolAddress((void**)&msgb,  g_msg);
    cudaGetSymbolAddress((void**)&sxb,   g_sx);
    cudaGetSymbolAddress((void**)&sxhb,  g_sxh);
    cudaGetSymbolAddress((void**)&sx2b,  g_sx2);
    cudaGetSymbolAddress((void**)&scaleb, g_scale);
    cudaGetSymbolAddress((void**)&shiftb, g_shift);
    cudaGetSymbolAddress((void**)&whi,   g_whi);
    cudaGetSymbolAddress((void**)&wlo,   g_wlo);

    cudaFuncSetAttribute(k_gemm_mma<0, 0>, cudaFuncAttributeMaxDynamicSharedMemorySize, GEMM_SMEM);
    cudaFuncSetAttribute(k_gemm_mma<1, 0>, cudaFuncAttributeMaxDynamicSharedMemorySize, GEMM_SMEM);
    cudaFuncSetAttribute(k_gemm_mma<0, 1>, cudaFuncAttributeMaxDynamicSharedMemorySize, GEMM_SMEM);
    cudaFuncSetAttribute(k_gemm_mma<0, 2>, cudaFuncAttributeMaxDynamicSharedMemorySize, GEMM_SMEM);

    // weight offsets (elements) in g_whi/g_wlo
    const size_t O_MSG1 = 0,       O_MSG2 = 98304,  O_N2S1 = 196608, O_N2S2 = 393216;
    const size_t O_S2N1 = 589824,  O_S2N2 = 786432, O_OUT1 = 983040, O_OUT2 = 1015808;
    const int PB = 256;
    auto prep = [&](const float* W, int K, int Nw, int cnt, size_t off) {
        int tot = cnt * K * Nw;
        k_prep<<<(tot + PB - 1) / PB, PB>>>(W, K, Nw, cnt, whi + off, wlo + off);
    };
    prep(msg_w1, HDIM, H2DIM, 3, O_MSG1);
    prep(msg_w2, H2DIM, HDIM, 3, O_MSG2);
    prep(n2s_w1, HDIM, H2DIM, 6, O_N2S1);
    prep(n2s_w2, H2DIM, HDIM, 6, O_N2S2);
    prep(s2n_w1, HDIM, H2DIM, 6, O_S2N1);
    prep(s2n_w2, H2DIM, HDIM, 6, O_S2N2);
    prep(out_w1, HDIM, H2DIM, 1, O_OUT1);
    prep(out_w2, H2DIM, HDIM, 1, O_OUT2);

    const int nh4 = N_NODES * HDIM / 4;
    const int sx4 = NSUB * HDIM / 4;
    dim3 gN2(2, (N_NODES + 127) / 128);
    dim3 gN1(1, (N_NODES + 127) / 128);
    dim3 gS2(2, (NSUB + 127) / 128);
    dim3 gS1(1, (NSUB + 127) / 128);
    const int scatterBlocksE = (N_EDGES * 32 + 255) / 256;
    const int scatterBlocksS = (ESUB * 32 + 255) / 256;

    k_copy4<<<blk4(N_NODES * HDIM), 256>>>(xb, x_in, nh4);

    for (int i = 0; i < NLAYERS; i++) {
        // GIN aggregation
        k_init_agg<<<blk4(N_NODES * HDIM), 256>>>(aggb, xb, eps_gin, i, nh4);
        k_scatter<<<scatterBlocksE, 256>>>(aggb, xb, edge, edge + N_EDGES, N_EDGES);

        // h = agg @ msg_w1 + b1
        k_gemm_mma<0, 0><<<gN2, 256, GEMM_SMEM>>>(
            aggb, whi + O_MSG1 + (size_t)i * HDIM * H2DIM, wlo + O_MSG1 + (size_t)i * HDIM * H2DIM,
            msg_b1 + (size_t)i * H2DIM, hb, N_NODES, HDIM, H2DIM, nullptr, nullptr);
        // BN stats
        k_zero_stats<<<1, 256>>>();
        k_colstats<<<2048, 256>>>(hb, N_NODES);
        k_bnfin<<<1, 256>>>(bn_g + (size_t)i * H2DIM, bn_b + (size_t)i * H2DIM,
                            1.0f / (float)N_NODES);
        // x = relu(bn(h)) @ msg_w2 + b2
        k_gemm_mma<1, 0><<<gN1, 256, GEMM_SMEM>>>(
            hb, whi + O_MSG2 + (size_t)i * H2DIM * HDIM, wlo + O_MSG2 + (size_t)i * H2DIM * HDIM,
            msg_b2 + (size_t)i * HDIM, xb, N_NODES, H2DIM, HDIM, scaleb, shiftb);

        for (int s = 0; s < NSUBT; s++) {
            const int* se = (s == 0) ? se0 : se1;
            const size_t widx = (size_t)i * NSUBT + s;

            k_zero4<<<blk4(NSUB * HDIM), 256>>>(sxb, sx4);
            k_scatter<<<scatterBlocksS, 256>>>(sxb, xb, se, se + ESUB, ESUB);

            k_gemm_mma<0, 1><<<gS2, 256, GEMM_SMEM>>>(
                sxb, whi + O_N2S1 + widx * HDIM * H2DIM, wlo + O_N2S1 + widx * HDIM * H2DIM,
                n2s_b1 + widx * H2DIM, sxhb, NSUB, HDIM, H2DIM, nullptr, nullptr);
            k_gemm_mma<0, 0><<<gS1, 256, GEMM_SMEM>>>(
                sxhb, whi + O_N2S2 + widx * H2DIM * HDIM, wlo + O_N2S2 + widx * H2DIM * HDIM,
                n2s_b2 + widx * HDIM, sx2b, NSUB, H2DIM, HDIM, nullptr, nullptr);

            k_zero4<<<blk4(N_NODES * HDIM), 256>>>(msgb, nh4);
            k_scatter<<<scatterBlocksS, 256>>>(msgb, sx2b, se + ESUB, se, ESUB);

            k_gemm_mma<0, 1><<<gN2, 256, GEMM_SMEM>>>(
                msgb, whi + O_S2N1 + widx * HDIM * H2DIM, wlo + O_S2N1 + widx * HDIM * H2DIM,
                s2n_b1 + widx * H2DIM, hb, N_NODES, HDIM, H2DIM, nullptr, nullptr);
            k_gemm_mma<0, 2><<<gN1, 256, GEMM_SMEM>>>(
                hb, whi + O_S2N2 + widx * H2DIM * HDIM, wlo + O_S2N2 + widx * H2DIM * HDIM,
                s2n_b2 + widx * HDIM, xb, N_NODES, H2DIM, HDIM, nullptr, nullptr);
        }
    }

    // output head
    k_gemm_mma<0, 1><<<gN2, 256, GEMM_SMEM>>>(
        xb, whi + O_OUT1, wlo + O_OUT1, out_b1, hb, N_NODES, HDIM, H2DIM, nullptr, nullptr);
    k_gemm_mma<0, 0><<<gN1, 256, GEMM_SMEM>>>(
        hb, whi + O_OUT2, wlo + O_OUT2, out_b2, (float*)d_out,
        N_NODES, H2DIM, OUTDIM, nullptr, nullptr);
}

// round 4
// speedup vs baseline: 1.6177x; 1.1521x over previous
#include <cuda_runtime.h>
#include <cuda_bf16.h>
#include <cstdint>

#define N_NODES 100000
#define HDIM 128
#define H2DIM 256
#define N_EDGES 600000
#define NSUB 20000
#define ESUB 200000
#define NLAYERS 3
#define NSUBT 2
#define OUTDIM 128

// ---------------- persistent scratch (static device globals; no allocs) ----
__device__ float g_x   [N_NODES * HDIM];
__device__ float g_agg [N_NODES * HDIM];
__device__ float g_h   [N_NODES * H2DIM];
__device__ float g_msg [N_NODES * HDIM];
__device__ float g_sx  [NSUB * HDIM];
__device__ float g_sxh [NSUB * H2DIM];
__device__ float g_sx2 [NSUB * HDIM];
__device__ float g_sum  [H2DIM];
__device__ float g_sumsq[H2DIM];
__device__ float g_scale[H2DIM];
__device__ float g_shift[H2DIM];
#define W_TOTAL 1048576
__device__ __nv_bfloat16 g_whi[W_TOTAL];
__device__ __nv_bfloat16 g_wlo[W_TOTAL];

// ---------------- small utility kernels ------------------------------------
__global__ void k_copy4(float* __restrict__ dst, const float* __restrict__ src, int n4) {
    int i = blockIdx.x * blockDim.x + threadIdx.x;
    if (i < n4) reinterpret_cast<float4*>(dst)[i] = reinterpret_cast<const float4*>(src)[i];
}
__global__ void k_zero4(float* __restrict__ dst, int n4) {
    int i = blockIdx.x * blockDim.x + threadIdx.x;
    if (i < n4) reinterpret_cast<float4*>(dst)[i] = make_float4(0.f, 0.f, 0.f, 0.f);
}
__global__ void k_init_agg(float* __restrict__ agg, const float* __restrict__ x,
                           const float* __restrict__ eps, int layer, int n4) {
    int i = blockIdx.x * blockDim.x + threadIdx.x;
    if (i >= n4) return;
    float e = 1.0f + __ldg(eps + layer);
    float4 v = reinterpret_cast<const float4*>(x)[i];
    v.x *= e; v.y *= e; v.z *= e; v.w *= e;
    reinterpret_cast<float4*>(agg)[i] = v;
}
// out[didx[e]] += in[sidx[e]] : one warp/edge, float4 gather + v4 red atomics
__global__ void k_scatter(float* __restrict__ out, const float* __restrict__ in,
                          const int* __restrict__ sidx, const int* __restrict__ didx, int nE) {
    int w = (blockIdx.x * blockDim.x + threadIdx.x) >> 5;
    if (w >= nE) return;
    int lane = threadIdx.x & 31;
    int s = __ldg(sidx + w);
    int d = __ldg(didx + w);
    float4 v = *reinterpret_cast<const float4*>(in + (size_t)s * HDIM + lane * 4);
    float* op = out + (size_t)d * HDIM + lane * 4;
    asm volatile("red.global.add.v4.f32 [%0], {%1,%2,%3,%4};"
                 :: "l"(op), "f"(v.x), "f"(v.y), "f"(v.z), "f"(v.w) : "memory");
}
__global__ void k_zero_stats() {
    g_sum[threadIdx.x] = 0.f;
    g_sumsq[threadIdx.x] = 0.f;
}
// per-column sum / sumsq of h[M,256]: float4 reads, smem block-reduce
__global__ void k_colstats(const float* __restrict__ h, int M) {
    __shared__ float bs[4][H2DIM];
    __shared__ float bss[4][H2DIM];
    int t = threadIdx.x;
    int c4 = (t & 63) * 4;
    int rs = t >> 6;  // 0..3
    float4 s = make_float4(0.f, 0.f, 0.f, 0.f);
    float4 ss = make_float4(0.f, 0.f, 0.f, 0.f);
    for (int r = blockIdx.x * 4 + rs; r < M; r += gridDim.x * 4) {
        float4 v = *reinterpret_cast<const float4*>(h + (size_t)r * H2DIM + c4);
        s.x += v.x; s.y += v.y; s.z += v.z; s.w += v.w;
        ss.x += v.x * v.x; ss.y += v.y * v.y; ss.z += v.z * v.z; ss.w += v.w * v.w;
    }
    *reinterpret_cast<float4*>(&bs[rs][c4]) = s;
    *reinterpret_cast<float4*>(&bss[rs][c4]) = ss;
    __syncthreads();
    if (rs == 0) {
#pragma unroll
        for (int j = 1; j < 4; j++) {
            float4 a = *reinterpret_cast<float4*>(&bs[j][c4]);
            float4 b = *reinterpret_cast<float4*>(&bss[j][c4]);
            s.x += a.x; s.y += a.y; s.z += a.z; s.w += a.w;
            ss.x += b.x; ss.y += b.y; ss.z += b.z; ss.w += b.w;
        }
        atomicAdd(&g_sum[c4 + 0], s.x); atomicAdd(&g_sum[c4 + 1], s.y);
        atomicAdd(&g_sum[c4 + 2], s.z); atomicAdd(&g_sum[c4 + 3], s.w);
        atomicAdd(&g_sumsq[c4 + 0], ss.x); atomicAdd(&g_sumsq[c4 + 1], ss.y);
        atomicAdd(&g_sumsq[c4 + 2], ss.z); atomicAdd(&g_sumsq[c4 + 3], ss.w);
    }
}
__global__ void k_bnfin(const float* __restrict__ gamma, const float* __restrict__ beta,
                        float invM) {
    int c = threadIdx.x;
    float mean = g_sum[c] * invM;
    float var  = g_sumsq[c] * invM - mean * mean;
    float sc   = __ldg(gamma + c) * rsqrtf(var + 1e-5f);
    g_scale[c] = sc;
    g_shift[c] = __ldg(beta + c) - mean * sc;
}
// split fp32 weight [cnt][K,Nw] -> transposed bf16 hi/lo [cnt][Nw,K]
__global__ void k_prep(const float* __restrict__ W, int K, int Nw, int cnt,
                       __nv_bfloat16* __restrict__ hi, __nv_bfloat16* __restrict__ lo) {
    int i = blockIdx.x * blockDim.x + threadIdx.x;
    int per = K * Nw;
    if (i >= cnt * per) return;
    int m = i / per, r = i % per;
    int k = r / Nw, n = r % Nw;
    float w = W[i];
    __nv_bfloat16 h = __float2bfloat16(w);
    float res = w - __bfloat162float(h);
    size_t o = (size_t)m * per + (size_t)n * K + k;
    hi[o] = h;
    lo[o] = __float2bfloat16(res);
}

// ---------------- mma.sync helpers ------------------------------------------
__device__ __forceinline__ uint32_t smem_u32(const void* p) {
    uint32_t a;
    asm("{ .reg .u64 t; cvta.to.shared.u64 t, %1; cvt.u32.u64 %0, t; }" : "=r"(a) : "l"(p));
    return a;
}
__device__ __forceinline__ void ldsm_x4(uint32_t* r, uint32_t addr) {
    asm volatile("ldmatrix.sync.aligned.m8n8.x4.shared.b16 {%0,%1,%2,%3}, [%4];"
                 : "=r"(r[0]), "=r"(r[1]), "=r"(r[2]), "=r"(r[3]) : "r"(addr));
}
__device__ __forceinline__ void mma16816(float* d, const uint32_t* a, uint32_t b0, uint32_t b1) {
    asm volatile(
        "mma.sync.aligned.m16n8k16.row.col.f32.bf16.bf16.f32 "
        "{%0,%1,%2,%3}, {%4,%5,%6,%7}, {%8,%9}, {%0,%1,%2,%3};"
        : "+f"(d[0]), "+f"(d[1]), "+f"(d[2]), "+f"(d[3])
        : "r"(a[0]), "r"(a[1]), "r"(a[2]), "r"(a[3]), "r"(b0), "r"(b1));
}
__device__ __forceinline__ void cp_async16(uint32_t dst, const void* src) {
    asm volatile("cp.async.cg.shared.global [%0], [%1], 16;" :: "r"(dst), "l"(src));
}

// ---------------- mma.sync split-bf16 GEMM ----------------------------------
// C[M,Nw] = op(A[M,K]) @ B[K,Nw] (+bias, epilogue), D += Ahi*Bhi + Alo*Bhi + Ahi*Blo
// AOP: 0 identity, 1 relu(A*scale[k]+shift[k]) fused BN
// EOP: 0 +bias ; 1 relu(+bias) ; 2 C += acc+bias (residual)
// 128x128 CTA tile, 8 warps (4M x 2N), warp tile 32x64, BK=64 chunks.
// SMEM tiles 128x64 bf16 (16KB each), row stride 128B, swizzle c16 ^= (r&7).
#define S_AHI 0
#define S_ALO 16384
#define S_BHI 32768
#define S_BLO 49152
#define GEMM_SMEM 65536

template <int AOP, int EOP>
__global__ __launch_bounds__(256, 2) void k_gemm_mma(
    const float* __restrict__ A, const __nv_bfloat16* __restrict__ Bhi,
    const __nv_bfloat16* __restrict__ Blo, const float* __restrict__ bias,
    float* __restrict__ C, int M, int K, int Nw,
    const float* __restrict__ scale, const float* __restrict__ shift) {
    extern __shared__ char smem[];
    const uint32_t sbase = smem_u32(smem);
    const int tid = threadIdx.x;
    const int wid = tid >> 5;
    const int lane = tid & 31;
    const int row0 = blockIdx.y * 128;
    const int col0 = blockIdx.x * 128;
    const int wm = (wid & 3) * 32;   // warp M offset
    const int wn = (wid >> 2) * 64;  // warp N offset

    float acc[2][8][4];
#pragma unroll
    for (int i = 0; i < 2; i++)
#pragma unroll
        for (int j = 0; j < 8; j++)
#pragma unroll
            for (int q = 0; q < 4; q++) acc[i][j][q] = 0.f;

    for (int chunk = 0; chunk < K; chunk += 64) {
        // ---- B tiles via cp.async (pure bf16 copies) ----
#pragma unroll
        for (int it = 0; it < 4; it++) {
            int task = tid + it * 256;
            int r = task >> 3;     // n-row 0..127
            int c16 = task & 7;    // 16B chunk
            uint32_t soff = (uint32_t)r * 128u + (uint32_t)((c16 ^ (r & 7)) << 4);
            const __nv_bfloat16* bh = Bhi + (size_t)(col0 + r) * K + chunk + c16 * 8;
            const __nv_bfloat16* bl = Blo + (size_t)(col0 + r) * K + chunk + c16 * 8;
            cp_async16(sbase + S_BHI + soff, bh);
            cp_async16(sbase + S_BLO + soff, bl);
        }
        asm volatile("cp.async.commit_group;" ::: "memory");

        // ---- A tile: fp32 -> (AOP) -> hi/lo bf16, swizzled store ----
#pragma unroll
        for (int it = 0; it < 4; it++) {
            int task = tid + it * 256;
            int r = task >> 3;
            int c16 = task & 7;
            uint32_t soff = (uint32_t)r * 128u + (uint32_t)((c16 ^ (r & 7)) << 4);
            float4 v0 = make_float4(0.f, 0.f, 0.f, 0.f), v1 = v0;
            if (row0 + r < M) {
                const float* ap = A + (size_t)(row0 + r) * K + chunk + c16 * 8;
                v0 = *reinterpret_cast<const float4*>(ap);
                v1 = *reinterpret_cast<const float4*>(ap + 4);
                if (AOP == 1) {
                    int gk = chunk + c16 * 8;
                    float4 sc0 = *reinterpret_cast<const float4*>(scale + gk);
                    float4 sc1 = *reinterpret_cast<const float4*>(scale + gk + 4);
                    float4 sh0 = *reinterpret_cast<const float4*>(shift + gk);
                    float4 sh1 = *reinterpret_cast<const float4*>(shift + gk + 4);
                    v0.x = fmaxf(fmaf(v0.x, sc0.x, sh0.x), 0.f);
                    v0.y = fmaxf(fmaf(v0.y, sc0.y, sh0.y), 0.f);
                    v0.z = fmaxf(fmaf(v0.z, sc0.z, sh0.z), 0.f);
                    v0.w = fmaxf(fmaf(v0.w, sc0.w, sh0.w), 0.f);
                    v1.x = fmaxf(fmaf(v1.x, sc1.x, sh1.x), 0.f);
                    v1.y = fmaxf(fmaf(v1.y, sc1.y, sh1.y), 0.f);
                    v1.z = fmaxf(fmaf(v1.z, sc1.z, sh1.z), 0.f);
                    v1.w = fmaxf(fmaf(v1.w, sc1.w, sh1.w), 0.f);
                }
            }
            __nv_bfloat162 h01 = __float22bfloat162_rn(make_float2(v0.x, v0.y));
            __nv_bfloat162 h23 = __float22bfloat162_rn(make_float2(v0.z, v0.w));
            __nv_bfloat162 h45 = __float22bfloat162_rn(make_float2(v1.x, v1.y));
            __nv_bfloat162 h67 = __float22bfloat162_rn(make_float2(v1.z, v1.w));
            float2 f01 = __bfloat1622float2(h01), f23 = __bfloat1622float2(h23);
            float2 f45 = __bfloat1622float2(h45), f67 = __bfloat1622float2(h67);
            __nv_bfloat162 l01 = __float22bfloat162_rn(make_float2(v0.x - f01.x, v0.y - f01.y));
            __nv_bfloat162 l23 = __float22bfloat162_rn(make_float2(v0.z - f23.x, v0.w - f23.y));
            __nv_bfloat162 l45 = __float22bfloat162_rn(make_float2(v1.x - f45.x, v1.y - f45.y));
            __nv_bfloat162 l67 = __float22bfloat162_rn(make_float2(v1.z - f67.x, v1.w - f67.y));
            uint4 hp, lp;
            hp.x = *(uint32_t*)&h01; hp.y = *(uint32_t*)&h23;
            hp.z = *(uint32_t*)&h45; hp.w = *(uint32_t*)&h67;
            lp.x = *(uint32_t*)&l01; lp.y = *(uint32_t*)&l23;
            lp.z = *(uint32_t*)&l45; lp.w = *(uint32_t*)&l67;
            *reinterpret_cast<uint4*>(smem + S_AHI + soff) = hp;
            *reinterpret_cast<uint4*>(smem + S_ALO + soff) = lp;
        }
        asm volatile("cp.async.wait_group 0;" ::: "memory");
        __syncthreads();

        // ---- compute: 4 ksteps of 16 ----
#pragma unroll
        for (int ks = 0; ks < 4; ks++) {
            uint32_t ahi[2][4], alo[2][4];
#pragma unroll
            for (int ms = 0; ms < 2; ms++) {
                int r = wm + ms * 16 + (lane & 15);
                int c16 = ks * 2 + (lane >> 4);
                uint32_t off = (uint32_t)r * 128u + (uint32_t)(((c16 ^ (r & 7))) << 4);
                ldsm_x4(ahi[ms], sbase + S_AHI + off);
                ldsm_x4(alo[ms], sbase + S_ALO + off);
            }
#pragma unroll
            for (int p = 0; p < 4; p++) {
                int n = wn + p * 16 + ((lane >> 4) << 3) + (lane & 7);
                int c16 = ks * 2 + ((lane >> 3) & 1);
                uint32_t off = (uint32_t)n * 128u + (uint32_t)(((c16 ^ (n & 7))) << 4);
                uint32_t bh[4], bl[4];
                ldsm_x4(bh, sbase + S_BHI + off);
                ldsm_x4(bl, sbase + S_BLO + off);
#pragma unroll
                for (int ms = 0; ms < 2; ms++) {
                    mma16816(acc[ms][2 * p],     ahi[ms], bh[0], bh[1]);
                    mma16816(acc[ms][2 * p + 1], ahi[ms], bh[2], bh[3]);
                    mma16816(acc[ms][2 * p],     alo[ms], bh[0], bh[1]);
                    mma16816(acc[ms][2 * p + 1], alo[ms], bh[2], bh[3]);
                    mma16816(acc[ms][2 * p],     ahi[ms], bl[0], bl[1]);
                    mma16816(acc[ms][2 * p + 1], ahi[ms], bl[2], bl[3]);
                }
            }
        }
        __syncthreads();
    }

    // ---- epilogue: register fragments -> C ----
#pragma unroll
    for (int ms = 0; ms < 2; ms++) {
#pragma unroll
        for (int nt = 0; nt < 8; nt++) {
            int c = col0 + wn + nt * 8 + (lane & 3) * 2;
            float2 bi = *reinterpret_cast<const float2*>(bias + c);
            int r = row0 + wm + ms * 16 + (lane >> 2);
#pragma unroll
            for (int half = 0; half < 2; half++) {
                int rr = r + half * 8;
                if (rr >= M) continue;
                float2 v;
                v.x = acc[ms][nt][2 * half + 0] + bi.x;
                v.y = acc[ms][nt][2 * half + 1] + bi.y;
                if (EOP == 1) { v.x = fmaxf(v.x, 0.f); v.y = fmaxf(v.y, 0.f); }
                float* cp = C + (size_t)rr * Nw + c;
                if (EOP == 2) {
                    float2 o = *reinterpret_cast<const float2*>(cp);
                    v.x += o.x; v.y += o.y;
                }
                *reinterpret_cast<float2*>(cp) = v;
            }
        }
    }
}

// ---------------- host orchestration ---------------------------------------
static inline int blk4(int n) { return (n / 4 + 255) / 256; }

extern "C" void kernel_launch(void* const* d_in, const int* in_sizes, int n_in,
                              void* d_out, int out_size) {
    const float* x_in    = (const float*)d_in[0];
    const int*   edge    = (const int*)d_in[1];
    const int*   se0     = (const int*)d_in[2];
    const int*   se1     = (const int*)d_in[3];
    const float* msg_w1  = (const float*)d_in[4];
    const float* msg_b1  = (const float*)d_in[5];
    const float* bn_g    = (const float*)d_in[6];
    const float* bn_b    = (const float*)d_in[7];
    const float* msg_w2  = (const float*)d_in[8];
    const float* msg_b2  = (const float*)d_in[9];
    const float* eps_gin = (const float*)d_in[10];
    const float* n2s_w1  = (const float*)d_in[11];
    const float* n2s_b1  = (const float*)d_in[12];
    const float* n2s_w2  = (const float*)d_in[13];
    const float* n2s_b2  = (const float*)d_in[14];
    const float* s2n_w1  = (const float*)d_in[15];
    const float* s2n_b1  = (const float*)d_in[16];
    const float* s2n_w2  = (const float*)d_in[17];
    const float* s2n_b2  = (const float*)d_in[18];
    const float* out_w1  = (const float*)d_in[19];
    const float* out_b1  = (const float*)d_in[20];
    const float* out_w2  = (const float*)d_in[21];
    const float* out_b2  = (const float*)d_in[22];

    float *xb, *aggb, *hb, *msgb, *sxb, *sxhb, *sx2b, *scaleb, *shiftb;
    __nv_bfloat16 *whi, *wlo;
    cudaGetSymbolAddress((void**)&xb,    g_x);
    cudaGetSymbolAddress((void**)&aggb,  g_agg);
    cudaGetSymbolAddress((void**)&hb,    g_h);
    cudaGetSymbolAddress((void**)&msgb,  g_msg);
    cudaGetSymbolAddress((void**)&sxb,   g_sx);
    cudaGetSymbolAddress((void**)&sxhb,  g_sxh);
    cudaGetSymbolAddress((void**)&sx2b,  g_sx2);
    cudaGetSymbolAddress((void**)&scaleb, g_scale);
    cudaGetSymbolAddress((void**)&shiftb, g_shift);
    cudaGetSymbolAddress((void**)&whi,   g_whi);
    cudaGetSymbolAddress((void**)&wlo,   g_wlo);

    cudaFuncSetAttribute(k_gemm_mma<0, 0>, cudaFuncAttributeMaxDynamicSharedMemorySize, GEMM_SMEM);
    cudaFuncSetAttribute(k_gemm_mma<1, 0>, cudaFuncAttributeMaxDynamicSharedMemorySize, GEMM_SMEM);
    cudaFuncSetAttribute(k_gemm_mma<0, 1>, cudaFuncAttributeMaxDynamicSharedMemorySize, GEMM_SMEM);
    cudaFuncSetAttribute(k_gemm_mma<0, 2>, cudaFuncAttributeMaxDynamicSharedMemorySize, GEMM_SMEM);

    // weight offsets (elements) in g_whi/g_wlo
    const size_t O_MSG1 = 0,       O_MSG2 = 98304,  O_N2S1 = 196608, O_N2S2 = 393216;
    const size_t O_S2N1 = 589824,  O_S2N2 = 786432, O_OUT1 = 983040, O_OUT2 = 1015808;
    const int PB = 256;
    auto prep = [&](const float* W, int K, int Nw, int cnt, size_t off) {
        int tot = cnt * K * Nw;
        k_prep<<<(tot + PB - 1) / PB, PB>>>(W, K, Nw, cnt, whi + off, wlo + off);
    };
    prep(msg_w1, HDIM, H2DIM, 3, O_MSG1);
    prep(msg_w2, H2DIM, HDIM, 3, O_MSG2);
    prep(n2s_w1, HDIM, H2DIM, 6, O_N2S1);
    prep(n2s_w2, H2DIM, HDIM, 6, O_N2S2);
    prep(s2n_w1, HDIM, H2DIM, 6, O_S2N1);
    prep(s2n_w2, H2DIM, HDIM, 6, O_S2N2);
    prep(out_w1, HDIM, H2DIM, 1, O_OUT1);
    prep(out_w2, H2DIM, HDIM, 1, O_OUT2);

    const int nh4 = N_NODES * HDIM / 4;
    const int sx4 = NSUB * HDIM / 4;
    dim3 gN2(2, (N_NODES + 127) / 128);
    dim3 gN1(1, (N_NODES + 127) / 128);
    dim3 gS2(2, (NSUB + 127) / 128);
    dim3 gS1(1, (NSUB + 127) / 128);
    const int scatterBlocksE = (N_EDGES * 32 + 255) / 256;
    const int scatterBlocksS = (ESUB * 32 + 255) / 256;

    k_copy4<<<blk4(N_NODES * HDIM), 256>>>(xb, x_in, nh4);

    for (int i = 0; i < NLAYERS; i++) {
        // GIN aggregation
        k_init_agg<<<blk4(N_NODES * HDIM), 256>>>(aggb, xb, eps_gin, i, nh4);
        k_scatter<<<scatterBlocksE, 256>>>(aggb, xb, edge, edge + N_EDGES, N_EDGES);

        // h = agg @ msg_w1 + b1
        k_gemm_mma<0, 0><<<gN2, 256, GEMM_SMEM>>>(
            aggb, whi + O_MSG1 + (size_t)i * HDIM * H2DIM, wlo + O_MSG1 + (size_t)i * HDIM * H2DIM,
            msg_b1 + (size_t)i * H2DIM, hb, N_NODES, HDIM, H2DIM, nullptr, nullptr);
        // BN stats
        k_zero_stats<<<1, 256>>>();
        k_colstats<<<296, 256>>>(hb, N_NODES);
        k_bnfin<<<1, 256>>>(bn_g + (size_t)i * H2DIM, bn_b + (size_t)i * H2DIM,
                            1.0f / (float)N_NODES);
        // x = relu(bn(h)) @ msg_w2 + b2
        k_gemm_mma<1, 0><<<gN1, 256, GEMM_SMEM>>>(
            hb, whi + O_MSG2 + (size_t)i * H2DIM * HDIM, wlo + O_MSG2 + (size_t)i * H2DIM * HDIM,
            msg_b2 + (size_t)i * HDIM, xb, N_NODES, H2DIM, HDIM, scaleb, shiftb);

        for (int s = 0; s < NSUBT; s++) {
            const int* se = (s == 0) ? se0 : se1;
            const size_t widx = (size_t)i * NSUBT + s;

            k_zero4<<<blk4(NSUB * HDIM), 256>>>(sxb, sx4);
            k_scatter<<<scatterBlocksS, 256>>>(sxb, xb, se, se + ESUB, ESUB);

            k_gemm_mma<0, 1><<<gS2, 256, GEMM_SMEM>>>(
                sxb, whi + O_N2S1 + widx * HDIM * H2DIM, wlo + O_N2S1 + widx * HDIM * H2DIM,
                n2s_b1 + widx * H2DIM, sxhb, NSUB, HDIM, H2DIM, nullptr, nullptr);
            k_gemm_mma<0, 0><<<gS1, 256, GEMM_SMEM>>>(
                sxhb, whi + O_N2S2 + widx * H2DIM * HDIM, wlo + O_N2S2 + widx * H2DIM * HDIM,
                n2s_b2 + widx * HDIM, sx2b, NSUB, H2DIM, HDIM, nullptr, nullptr);

            k_zero4<<<blk4(N_NODES * HDIM), 256>>>(msgb, nh4);
            k_scatter<<<scatterBlocksS, 256>>>(msgb, sx2b, se + ESUB, se, ESUB);

            k_gemm_mma<0, 1><<<gN2, 256, GEMM_SMEM>>>(
                msgb, whi + O_S2N1 + widx * HDIM * H2DIM, wlo + O_S2N1 + widx * HDIM * H2DIM,
                s2n_b1 + widx * H2DIM, hb, N_NODES, HDIM, H2DIM, nullptr, nullptr);
            k_gemm_mma<0, 2><<<gN1, 256, GEMM_SMEM>>>(
                hb, whi + O_S2N2 + widx * H2DIM * HDIM, wlo + O_S2N2 + widx * H2DIM * HDIM,
                s2n_b2 + widx * HDIM, xb, N_NODES, H2DIM, HDIM, nullptr, nullptr);
        }
    }

    // output head
    k_gemm_mma<0, 1><<<gN2, 256, GEMM_SMEM>>>(
        xb, whi + O_OUT1, wlo + O_OUT1, out_b1, hb, N_NODES, HDIM, H2DIM, nullptr, nullptr);
    k_gemm_mma<0, 0><<<gN1, 256, GEMM_SMEM>>>(
        hb, whi + O_OUT2, wlo + O_OUT2, out_b2, (float*)d_out,
        N_NODES, H2DIM, OUTDIM, nullptr, nullptr);
}

// round 5
// speedup vs baseline: 1.6470x; 1.0181x over previous
#include <cuda_runtime.h>
#include <cuda_bf16.h>
#include <cstdint>

#define N_NODES 100000
#define HDIM 128
#define H2DIM 256
#define N_EDGES 600000
#define NSUB 20000
#define ESUB 200000
#define NLAYERS 3
#define NSUBT 2
#define OUTDIM 128

// ---------------- persistent scratch (static device globals; no allocs) ----
__device__ float g_x   [N_NODES * HDIM];
__device__ float g_agg [N_NODES * HDIM];
__device__ float g_h   [N_NODES * H2DIM];
__device__ float g_msg [N_NODES * HDIM];
__device__ float g_sx  [NSUB * HDIM];
__device__ float g_sxh [NSUB * H2DIM];
__device__ float g_sx2 [NSUB * HDIM];
__device__ float g_sum  [H2DIM];
__device__ float g_sumsq[H2DIM];
__device__ float g_scale[H2DIM];
__device__ float g_shift[H2DIM];
#define W_TOTAL 1048576
__device__ __nv_bfloat16 g_whi[W_TOTAL];
__device__ __nv_bfloat16 g_wlo[W_TOTAL];
// CSR structures (rebuilt every launch)
__device__ int g_cnt   [N_NODES + 1];
__device__ int g_cursor[N_NODES + 1];
__device__ int g_off_e  [N_NODES + 1];
__device__ int g_off_s0c[NSUB + 1];
__device__ int g_off_s0r[N_NODES + 1];
__device__ int g_off_s1c[NSUB + 1];
__device__ int g_off_s1r[N_NODES + 1];
__device__ int g_csr_e  [N_EDGES];
__device__ int g_csr_s0c[ESUB];
__device__ int g_csr_s0r[ESUB];
__device__ int g_csr_s1c[ESUB];
__device__ int g_csr_s1r[ESUB];

// ---------------- CSR build kernels -----------------------------------------
__global__ void k_zeroi(int* __restrict__ p, int n) {
    int i = blockIdx.x * blockDim.x + threadIdx.x;
    if (i < n) p[i] = 0;
}
__global__ void k_hist(const int* __restrict__ didx, int* __restrict__ cnt, int nE) {
    int e = blockIdx.x * blockDim.x + threadIdx.x;
    if (e < nE) atomicAdd(&cnt[__ldg(didx + e)], 1);
}
// single-block exclusive scan: offs[0..n] and cursor[0..n-1]
__global__ void k_scan(const int* __restrict__ cnt, int* __restrict__ offs,
                       int* __restrict__ cursor, int n) {
    __shared__ int warp_sums[32];
    __shared__ int carry_s;
    int t = threadIdx.x, lane = t & 31, w = t >> 5;
    if (t == 0) carry_s = 0;
    __syncthreads();
    for (int base = 0; base < n; base += 1024) {
        int idx = base + t;
        int v = (idx < n) ? cnt[idx] : 0;
        int x = v;
#pragma unroll
        for (int d = 1; d < 32; d <<= 1) {
            int y = __shfl_up_sync(0xFFFFFFFFu, x, d);
            if (lane >= d) x += y;
        }
        if (lane == 31) warp_sums[w] = x;
        __syncthreads();
        if (w == 0) {
            int s = warp_sums[lane];
#pragma unroll
            for (int d = 1; d < 32; d <<= 1) {
                int y = __shfl_up_sync(0xFFFFFFFFu, s, d);
                if (lane >= d) s += y;
            }
            warp_sums[lane] = s;
        }
        __syncthreads();
        int woff = (w > 0) ? warp_sums[w - 1] : 0;
        int excl = x - v + woff + carry_s;
        if (idx < n) { offs[idx] = excl; cursor[idx] = excl; }
        __syncthreads();
        if (t == 0) carry_s += warp_sums[31];
        __syncthreads();
    }
    if (threadIdx.x == 0) offs[n] = carry_s;
}
__global__ void k_fill(const int* __restrict__ sidx, const int* __restrict__ didx,
                       int* __restrict__ cursor, int* __restrict__ csr, int nE) {
    int e = blockIdx.x * blockDim.x + threadIdx.x;
    if (e >= nE) return;
    int d = __ldg(didx + e);
    int pos = atomicAdd(&cursor[d], 1);
    csr[pos] = __ldg(sidx + e);
}

// ---------------- gather (replaces zero+scatter-atomics) --------------------
// out[node] = (BASE? (1+eps[layer])*basex[node] : 0) + sum_{j} in[srcs[j]]
template <int BASE>
__global__ void k_gather(float* __restrict__ out, const float* __restrict__ in,
                         const int* __restrict__ offs, const int* __restrict__ srcs,
                         const float* __restrict__ basex, const float* __restrict__ eps,
                         int layer, int nrows) {
    int node = blockIdx.x * 8 + (threadIdx.x >> 5);
    if (node >= nrows) return;
    int lane = threadIdx.x & 31;
    int b = __ldg(offs + node), e = __ldg(offs + node + 1);
    float4 acc;
    if (BASE == 1) {
        float cf = 1.0f + __ldg(eps + layer);
        float4 v = *reinterpret_cast<const float4*>(basex + (size_t)node * HDIM + lane * 4);
        acc = make_float4(cf * v.x, cf * v.y, cf * v.z, cf * v.w);
    } else {
        acc = make_float4(0.f, 0.f, 0.f, 0.f);
    }
    for (int j = b; j < e; j++) {
        int s = __ldg(srcs + j);
        float4 v = *reinterpret_cast<const float4*>(in + (size_t)s * HDIM + lane * 4);
        acc.x += v.x; acc.y += v.y; acc.z += v.z; acc.w += v.w;
    }
    *reinterpret_cast<float4*>(out + (size_t)node * HDIM + lane * 4) = acc;
}

// ---------------- BN stats ----------------------------------------------------
__global__ void k_zero_stats() {
    g_sum[threadIdx.x] = 0.f;
    g_sumsq[threadIdx.x] = 0.f;
}
__global__ void k_colstats(const float* __restrict__ h, int M) {
    __shared__ float bs[4][H2DIM];
    __shared__ float bss[4][H2DIM];
    int t = threadIdx.x;
    int c4 = (t & 63) * 4;
    int rs = t >> 6;
    float4 s = make_float4(0.f, 0.f, 0.f, 0.f);
    float4 ss = make_float4(0.f, 0.f, 0.f, 0.f);
    for (int r = blockIdx.x * 4 + rs; r < M; r += gridDim.x * 4) {
        float4 v = *reinterpret_cast<const float4*>(h + (size_t)r * H2DIM + c4);
        s.x += v.x; s.y += v.y; s.z += v.z; s.w += v.w;
        ss.x += v.x * v.x; ss.y += v.y * v.y; ss.z += v.z * v.z; ss.w += v.w * v.w;
    }
    *reinterpret_cast<float4*>(&bs[rs][c4]) = s;
    *reinterpret_cast<float4*>(&bss[rs][c4]) = ss;
    __syncthreads();
    if (rs == 0) {
#pragma unroll
        for (int j = 1; j < 4; j++) {
            float4 a = *reinterpret_cast<float4*>(&bs[j][c4]);
            float4 b = *reinterpret_cast<float4*>(&bss[j][c4]);
            s.x += a.x; s.y += a.y; s.z += a.z; s.w += a.w;
            ss.x += b.x; ss.y += b.y; ss.z += b.z; ss.w += b.w;
        }
        atomicAdd(&g_sum[c4 + 0], s.x); atomicAdd(&g_sum[c4 + 1], s.y);
        atomicAdd(&g_sum[c4 + 2], s.z); atomicAdd(&g_sum[c4 + 3], s.w);
        atomicAdd(&g_sumsq[c4 + 0], ss.x); atomicAdd(&g_sumsq[c4 + 1], ss.y);
        atomicAdd(&g_sumsq[c4 + 2], ss.z); atomicAdd(&g_sumsq[c4 + 3], ss.w);
    }
}
__global__ void k_bnfin(const float* __restrict__ gamma, const float* __restrict__ beta,
                        float invM) {
    int c = threadIdx.x;
    float mean = g_sum[c] * invM;
    float var  = g_sumsq[c] * invM - mean * mean;
    float sc   = __ldg(gamma + c) * rsqrtf(var + 1e-5f);
    g_scale[c] = sc;
    g_shift[c] = __ldg(beta + c) - mean * sc;
}
// split fp32 weight [cnt][K,Nw] -> transposed bf16 hi/lo [cnt][Nw,K]
__global__ void k_prep(const float* __restrict__ W, int K, int Nw, int cnt,
                       __nv_bfloat16* __restrict__ hi, __nv_bfloat16* __restrict__ lo) {
    int i = blockIdx.x * blockDim.x + threadIdx.x;
    int per = K * Nw;
    if (i >= cnt * per) return;
    int m = i / per, r = i % per;
    int k = r / Nw, n = r % Nw;
    float w = W[i];
    __nv_bfloat16 h = __float2bfloat16(w);
    float res = w - __bfloat162float(h);
    size_t o = (size_t)m * per + (size_t)n * K + k;
    hi[o] = h;
    lo[o] = __float2bfloat16(res);
}

// ---------------- mma.sync helpers ------------------------------------------
__device__ __forceinline__ uint32_t smem_u32(const void* p) {
    uint32_t a;
    asm("{ .reg .u64 t; cvta.to.shared.u64 t, %1; cvt.u32.u64 %0, t; }" : "=r"(a) : "l"(p));
    return a;
}
__device__ __forceinline__ void ldsm_x4(uint32_t* r, uint32_t addr) {
    asm volatile("ldmatrix.sync.aligned.m8n8.x4.shared.b16 {%0,%1,%2,%3}, [%4];"
                 : "=r"(r[0]), "=r"(r[1]), "=r"(r[2]), "=r"(r[3]) : "r"(addr));
}
__device__ __forceinline__ void mma16816(float* d, const uint32_t* a, uint32_t b0, uint32_t b1) {
    asm volatile(
        "mma.sync.aligned.m16n8k16.row.col.f32.bf16.bf16.f32 "
        "{%0,%1,%2,%3}, {%4,%5,%6,%7}, {%8,%9}, {%0,%1,%2,%3};"
        : "+f"(d[0]), "+f"(d[1]), "+f"(d[2]), "+f"(d[3])
        : "r"(a[0]), "r"(a[1]), "r"(a[2]), "r"(a[3]), "r"(b0), "r"(b1));
}
__device__ __forceinline__ void cp_async16(uint32_t dst, const void* src) {
    asm volatile("cp.async.cg.shared.global [%0], [%1], 16;" :: "r"(dst), "l"(src));
}

// ---------------- mma.sync split-bf16 GEMM ----------------------------------
#define S_AHI 0
#define S_ALO 16384
#define S_BHI 32768
#define S_BLO 49152
#define GEMM_SMEM 65536

template <int AOP, int EOP>
__global__ __launch_bounds__(256, 2) void k_gemm_mma(
    const float* __restrict__ A, const __nv_bfloat16* __restrict__ Bhi,
    const __nv_bfloat16* __restrict__ Blo, const float* __restrict__ bias,
    float* __restrict__ C, int M, int K, int Nw,
    const float* __restrict__ scale, const float* __restrict__ shift) {
    extern __shared__ char smem[];
    const uint32_t sbase = smem_u32(smem);
    const int tid = threadIdx.x;
    const int wid = tid >> 5;
    const int lane = tid & 31;
    const int row0 = blockIdx.y * 128;
    const int col0 = blockIdx.x * 128;
    const int wm = (wid & 3) * 32;
    const int wn = (wid >> 2) * 64;

    float acc[2][8][4];
#pragma unroll
    for (int i = 0; i < 2; i++)
#pragma unroll
        for (int j = 0; j < 8; j++)
#pragma unroll
            for (int q = 0; q < 4; q++) acc[i][j][q] = 0.f;

    for (int chunk = 0; chunk < K; chunk += 64) {
#pragma unroll
        for (int it = 0; it < 4; it++) {
            int task = tid + it * 256;
            int r = task >> 3;
            int c16 = task & 7;
            uint32_t soff = (uint32_t)r * 128u + (uint32_t)((c16 ^ (r & 7)) << 4);
            const __nv_bfloat16* bh = Bhi + (size_t)(col0 + r) * K + chunk + c16 * 8;
            const __nv_bfloat16* bl = Blo + (size_t)(col0 + r) * K + chunk + c16 * 8;
            cp_async16(sbase + S_BHI + soff, bh);
            cp_async16(sbase + S_BLO + soff, bl);
        }
        asm volatile("cp.async.commit_group;" ::: "memory");

#pragma unroll
        for (int it = 0; it < 4; it++) {
            int task = tid + it * 256;
            int r = task >> 3;
            int c16 = task & 7;
            uint32_t soff = (uint32_t)r * 128u + (uint32_t)((c16 ^ (r & 7)) << 4);
            float4 v0 = make_float4(0.f, 0.f, 0.f, 0.f), v1 = v0;
            if (row0 + r < M) {
                const float* ap = A + (size_t)(row0 + r) * K + chunk + c16 * 8;
                v0 = *reinterpret_cast<const float4*>(ap);
                v1 = *reinterpret_cast<const float4*>(ap + 4);
                if (AOP == 1) {
                    int gk = chunk + c16 * 8;
                    float4 sc0 = *reinterpret_cast<const float4*>(scale + gk);
                    float4 sc1 = *reinterpret_cast<const float4*>(scale + gk + 4);
                    float4 sh0 = *reinterpret_cast<const float4*>(shift + gk);
                    float4 sh1 = *reinterpret_cast<const float4*>(shift + gk + 4);
                    v0.x = fmaxf(fmaf(v0.x, sc0.x, sh0.x), 0.f);
                    v0.y = fmaxf(fmaf(v0.y, sc0.y, sh0.y), 0.f);
                    v0.z = fmaxf(fmaf(v0.z, sc0.z, sh0.z), 0.f);
                    v0.w = fmaxf(fmaf(v0.w, sc0.w, sh0.w), 0.f);
                    v1.x = fmaxf(fmaf(v1.x, sc1.x, sh1.x), 0.f);
                    v1.y = fmaxf(fmaf(v1.y, sc1.y, sh1.y), 0.f);
                    v1.z = fmaxf(fmaf(v1.z, sc1.z, sh1.z), 0.f);
                    v1.w = fmaxf(fmaf(v1.w, sc1.w, sh1.w), 0.f);
                }
            }
            __nv_bfloat162 h01 = __float22bfloat162_rn(make_float2(v0.x, v0.y));
            __nv_bfloat162 h23 = __float22bfloat162_rn(make_float2(v0.z, v0.w));
            __nv_bfloat162 h45 = __float22bfloat162_rn(make_float2(v1.x, v1.y));
            __nv_bfloat162 h67 = __float22bfloat162_rn(make_float2(v1.z, v1.w));
            float2 f01 = __bfloat1622float2(h01), f23 = __bfloat1622float2(h23);
            float2 f45 = __bfloat1622float2(h45), f67 = __bfloat1622float2(h67);
            __nv_bfloat162 l01 = __float22bfloat162_rn(make_float2(v0.x - f01.x, v0.y - f01.y));
            __nv_bfloat162 l23 = __float22bfloat162_rn(make_float2(v0.z - f23.x, v0.w - f23.y));
            __nv_bfloat162 l45 = __float22bfloat162_rn(make_float2(v1.x - f45.x, v1.y - f45.y));
            __nv_bfloat162 l67 = __float22bfloat162_rn(make_float2(v1.z - f67.x, v1.w - f67.y));
            uint4 hp, lp;
            hp.x = *(uint32_t*)&h01; hp.y = *(uint32_t*)&h23;
            hp.z = *(uint32_t*)&h45; hp.w = *(uint32_t*)&h67;
            lp.x = *(uint32_t*)&l01; lp.y = *(uint32_t*)&l23;
            lp.z = *(uint32_t*)&l45; lp.w = *(uint32_t*)&l67;
            *reinterpret_cast<uint4*>(smem + S_AHI + soff) = hp;
            *reinterpret_cast<uint4*>(smem + S_ALO + soff) = lp;
        }
        asm volatile("cp.async.wait_group 0;" ::: "memory");
        __syncthreads();

#pragma unroll
        for (int ks = 0; ks < 4; ks++) {
            uint32_t ahi[2][4], alo[2][4];
#pragma unroll
            for (int ms = 0; ms < 2; ms++) {
                int r = wm + ms * 16 + (lane & 15);
                int c16 = ks * 2 + (lane >> 4);
                uint32_t off = (uint32_t)r * 128u + (uint32_t)(((c16 ^ (r & 7))) << 4);
                ldsm_x4(ahi[ms], sbase + S_AHI + off);
                ldsm_x4(alo[ms], sbase + S_ALO + off);
            }
#pragma unroll
            for (int p = 0; p < 4; p++) {
                int n = wn + p * 16 + ((lane >> 4) << 3) + (lane & 7);
                int c16 = ks * 2 + ((lane >> 3) & 1);
                uint32_t off = (uint32_t)n * 128u + (uint32_t)(((c16 ^ (n & 7))) << 4);
                uint32_t bh[4], bl[4];
                ldsm_x4(bh, sbase + S_BHI + off);
                ldsm_x4(bl, sbase + S_BLO + off);
#pragma unroll
                for (int ms = 0; ms < 2; ms++) {
                    mma16816(acc[ms][2 * p],     ahi[ms], bh[0], bh[1]);
                    mma16816(acc[ms][2 * p + 1], ahi[ms], bh[2], bh[3]);
                    mma16816(acc[ms][2 * p],     alo[ms], bh[0], bh[1]);
                    mma16816(acc[ms][2 * p + 1], alo[ms], bh[2], bh[3]);
                    mma16816(acc[ms][2 * p],     ahi[ms], bl[0], bl[1]);
                    mma16816(acc[ms][2 * p + 1], ahi[ms], bl[2], bl[3]);
                }
            }
        }
        __syncthreads();
    }

#pragma unroll
    for (int ms = 0; ms < 2; ms++) {
#pragma unroll
        for (int nt = 0; nt < 8; nt++) {
            int c = col0 + wn + nt * 8 + (lane & 3) * 2;
            float2 bi = *reinterpret_cast<const float2*>(bias + c);
            int r = row0 + wm + ms * 16 + (lane >> 2);
#pragma unroll
            for (int half = 0; half < 2; half++) {
                int rr = r + half * 8;
                if (rr >= M) continue;
                float2 v;
                v.x = acc[ms][nt][2 * half + 0] + bi.x;
                v.y = acc[ms][nt][2 * half + 1] + bi.y;
                if (EOP == 1) { v.x = fmaxf(v.x, 0.f); v.y = fmaxf(v.y, 0.f); }
                float* cp = C + (size_t)rr * Nw + c;
                if (EOP == 2) {
                    float2 o = *reinterpret_cast<const float2*>(cp);
                    v.x += o.x; v.y += o.y;
                }
                *reinterpret_cast<float2*>(cp) = v;
            }
        }
    }
}

// ---------------- host orchestration ---------------------------------------
extern "C" void kernel_launch(void* const* d_in, const int* in_sizes, int n_in,
                              void* d_out, int out_size) {
    const float* x_in    = (const float*)d_in[0];
    const int*   edge    = (const int*)d_in[1];
    const int*   se0     = (const int*)d_in[2];
    const int*   se1     = (const int*)d_in[3];
    const float* msg_w1  = (const float*)d_in[4];
    const float* msg_b1  = (const float*)d_in[5];
    const float* bn_g    = (const float*)d_in[6];
    const float* bn_b    = (const float*)d_in[7];
    const float* msg_w2  = (const float*)d_in[8];
    const float* msg_b2  = (const float*)d_in[9];
    const float* eps_gin = (const float*)d_in[10];
    const float* n2s_w1  = (const float*)d_in[11];
    const float* n2s_b1  = (const float*)d_in[12];
    const float* n2s_w2  = (const float*)d_in[13];
    const float* n2s_b2  = (const float*)d_in[14];
    const float* s2n_w1  = (const float*)d_in[15];
    const float* s2n_b1  = (const float*)d_in[16];
    const float* s2n_w2  = (const float*)d_in[17];
    const float* s2n_b2  = (const float*)d_in[18];
    const float* out_w1  = (const float*)d_in[19];
    const float* out_b1  = (const float*)d_in[20];
    const float* out_w2  = (const float*)d_in[21];
    const float* out_b2  = (const float*)d_in[22];

    float *xb, *aggb, *hb, *msgb, *sxb, *sxhb, *sx2b, *scaleb, *shiftb;
    __nv_bfloat16 *whi, *wlo;
    int *cnt, *cursor, *off_e, *off_s0c, *off_s0r, *off_s1c, *off_s1r;
    int *csr_e, *csr_s0c, *csr_s0r, *csr_s1c, *csr_s1r;
    cudaGetSymbolAddress((void**)&xb,    g_x);
    cudaGetSymbolAddress((void**)&aggb,  g_agg);
    cudaGetSymbolAddress((void**)&hb,    g_h);
    cudaGetSymbolAddress((void**)&msgb,  g_msg);
    cudaGetSymbolAddress((void**)&sxb,   g_sx);
    cudaGetSymbolAddress((void**)&sxhb,  g_sxh);
    cudaGetSymbolAddress((void**)&sx2b,  g_sx2);
    cudaGetSymbolAddress((void**)&scaleb, g_scale);
    cudaGetSymbolAddress((void**)&shiftb, g_shift);
    cudaGetSymbolAddress((void**)&whi,   g_whi);
    cudaGetSymbolAddress((void**)&wlo,   g_wlo);
    cudaGetSymbolAddress((void**)&cnt,    g_cnt);
    cudaGetSymbolAddress((void**)&cursor, g_cursor);
    cudaGetSymbolAddress((void**)&off_e,   g_off_e);
    cudaGetSymbolAddress((void**)&off_s0c, g_off_s0c);
    cudaGetSymbolAddress((void**)&off_s0r, g_off_s0r);
    cudaGetSymbolAddress((void**)&off_s1c, g_off_s1c);
    cudaGetSymbolAddress((void**)&off_s1r, g_off_s1r);
    cudaGetSymbolAddress((void**)&csr_e,   g_csr_e);
    cudaGetSymbolAddress((void**)&csr_s0c, g_csr_s0c);
    cudaGetSymbolAddress((void**)&csr_s0r, g_csr_s0r);
    cudaGetSymbolAddress((void**)&csr_s1c, g_csr_s1c);
    cudaGetSymbolAddress((void**)&csr_s1r, g_csr_s1r);

    cudaFuncSetAttribute(k_gemm_mma<0, 0>, cudaFuncAttributeMaxDynamicSharedMemorySize, GEMM_SMEM);
    cudaFuncSetAttribute(k_gemm_mma<1, 0>, cudaFuncAttributeMaxDynamicSharedMemorySize, GEMM_SMEM);
    cudaFuncSetAttribute(k_gemm_mma<0, 1>, cudaFuncAttributeMaxDynamicSharedMemorySize, GEMM_SMEM);
    cudaFuncSetAttribute(k_gemm_mma<0, 2>, cudaFuncAttributeMaxDynamicSharedMemorySize, GEMM_SMEM);

    auto build_csr = [&](const int* sidx, const int* didx, int nE, int nrows,
                         int* offs, int* csr) {
        k_zeroi<<<(nrows + 256) / 256, 256>>>(cnt, nrows + 1);
        k_hist<<<(nE + 255) / 256, 256>>>(didx, cnt, nE);
        k_scan<<<1, 1024>>>(cnt, offs, cursor, nrows);
        k_fill<<<(nE + 255) / 256, 256>>>(sidx, didx, cursor, csr, nE);
    };

    const size_t O_MSG1 = 0,       O_MSG2 = 98304,  O_N2S1 = 196608, O_N2S2 = 393216;
    const size_t O_S2N1 = 589824,  O_S2N2 = 786432, O_OUT1 = 983040, O_OUT2 = 1015808;
    const int PB = 256;
    auto prep = [&](const float* W, int K, int Nw, int cntw, size_t off) {
        int tot = cntw * K * Nw;
        k_prep<<<(tot + PB - 1) / PB, PB>>>(W, K, Nw, cntw, whi + off, wlo + off);
    };

    // --- launches 0-3: edge CSR ; 4: prep_msg1 ; 5: GIN gather (ncu target) ---
    build_csr(edge, edge + N_EDGES, N_EDGES, N_NODES, off_e, csr_e);
    prep(msg_w1, HDIM, H2DIM, 3, O_MSG1);
    const int gGN = (N_NODES + 7) / 8;
    const int gGS = (NSUB + 7) / 8;
    k_gather<1><<<gGN, 256>>>(aggb, x_in, off_e, csr_e, x_in, eps_gin, 0, N_NODES);

    // remaining preps + CSRs
    prep(msg_w2, H2DIM, HDIM, 3, O_MSG2);
    prep(n2s_w1, HDIM, H2DIM, 6, O_N2S1);
    prep(n2s_w2, H2DIM, HDIM, 6, O_N2S2);
    prep(s2n_w1, HDIM, H2DIM, 6, O_S2N1);
    prep(s2n_w2, H2DIM, HDIM, 6, O_S2N2);
    prep(out_w1, HDIM, H2DIM, 1, O_OUT1);
    prep(out_w2, H2DIM, HDIM, 1, O_OUT2);
    build_csr(se0, se0 + ESUB, ESUB, NSUB,    off_s0c, csr_s0c);  // by col, store row
    build_csr(se0 + ESUB, se0, ESUB, N_NODES, off_s0r, csr_s0r);  // by row, store col
    build_csr(se1, se1 + ESUB, ESUB, NSUB,    off_s1c, csr_s1c);
    build_csr(se1 + ESUB, se1, ESUB, N_NODES, off_s1r, csr_s1r);

    dim3 gN2(2, (N_NODES + 127) / 128);
    dim3 gN1(1, (N_NODES + 127) / 128);
    dim3 gS2(2, (NSUB + 127) / 128);
    dim3 gS1(1, (NSUB + 127) / 128);

    for (int i = 0; i < NLAYERS; i++) {
        // GIN aggregation (layer 0 done above)
        if (i > 0)
            k_gather<1><<<gGN, 256>>>(aggb, xb, off_e, csr_e, xb, eps_gin, i, N_NODES);

        // h = agg @ msg_w1 + b1
        k_gemm_mma<0, 0><<<gN2, 256, GEMM_SMEM>>>(
            aggb, whi + O_MSG1 + (size_t)i * HDIM * H2DIM, wlo + O_MSG1 + (size_t)i * HDIM * H2DIM,
            msg_b1 + (size_t)i * H2DIM, hb, N_NODES, HDIM, H2DIM, nullptr, nullptr);
        // BN stats
        k_zero_stats<<<1, 256>>>();
        k_colstats<<<296, 256>>>(hb, N_NODES);
        k_bnfin<<<1, 256>>>(bn_g + (size_t)i * H2DIM, bn_b + (size_t)i * H2DIM,
                            1.0f / (float)N_NODES);
        // x = relu(bn(h)) @ msg_w2 + b2
        k_gemm_mma<1, 0><<<gN1, 256, GEMM_SMEM>>>(
            hb, whi + O_MSG2 + (size_t)i * H2DIM * HDIM, wlo + O_MSG2 + (size_t)i * H2DIM * HDIM,
            msg_b2 + (size_t)i * HDIM, xb, N_NODES, H2DIM, HDIM, scaleb, shiftb);

        for (int s = 0; s < NSUBT; s++) {
            const int* offc = (s == 0) ? off_s0c : off_s1c;
            const int* csrc = (s == 0) ? csr_s0c : csr_s1c;
            const int* offr = (s == 0) ? off_s0r : off_s1r;
            const int* csrr = (s == 0) ? csr_s0r : csr_s1r;
            const size_t widx = (size_t)i * NSUBT + s;

            // sx[col] = sum x[row]
            k_gather<0><<<gGS, 256>>>(sxb, xb, offc, csrc, nullptr, nullptr, 0, NSUB);

            k_gemm_mma<0, 1><<<gS2, 256, GEMM_SMEM>>>(
                sxb, whi + O_N2S1 + widx * HDIM * H2DIM, wlo + O_N2S1 + widx * HDIM * H2DIM,
                n2s_b1 + widx * H2DIM, sxhb, NSUB, HDIM, H2DIM, nullptr, nullptr);
            k_gemm_mma<0, 0><<<gS1, 256, GEMM_SMEM>>>(
                sxhb, whi + O_N2S2 + widx * H2DIM * HDIM, wlo + O_N2S2 + widx * H2DIM * HDIM,
                n2s_b2 + widx * HDIM, sx2b, NSUB, H2DIM, HDIM, nullptr, nullptr);

            // msg[row] = sum sx2[col]
            k_gather<0><<<gGN, 256>>>(msgb, sx2b, offr, csrr, nullptr, nullptr, 0, N_NODES);

            k_gemm_mma<0, 1><<<gN2, 256, GEMM_SMEM>>>(
                msgb, whi + O_S2N1 + widx * HDIM * H2DIM, wlo + O_S2N1 + widx * HDIM * H2DIM,
                s2n_b1 + widx * H2DIM, hb, N_NODES, HDIM, H2DIM, nullptr, nullptr);
            k_gemm_mma<0, 2><<<gN1, 256, GEMM_SMEM>>>(
                hb, whi + O_S2N2 + widx * H2DIM * HDIM, wlo + O_S2N2 + widx * H2DIM * HDIM,
                s2n_b2 + widx * HDIM, xb, N_NODES, H2DIM, HDIM, nullptr, nullptr);
        }
    }

    // output head
    k_gemm_mma<0, 1><<<gN2, 256, GEMM_SMEM>>>(
        xb, whi + O_OUT1, wlo + O_OUT1, out_b1, hb, N_NODES, HDIM, H2DIM, nullptr, nullptr);
    k_gemm_mma<0, 0><<<gN1, 256, GEMM_SMEM>>>(
        hb, whi + O_OUT2, wlo + O_OUT2, out_b2, (float*)d_out,
        N_NODES, H2DIM, OUTDIM, nullptr, nullptr);
}

// round 6
// speedup vs baseline: 1.8110x; 1.0996x over previous
#include <cuda_runtime.h>
#include <cuda_bf16.h>
#include <cstdint>

#define N_NODES 100000
#define HDIM 128
#define H2DIM 256
#define N_EDGES 600000
#define NSUB 20000
#define ESUB 200000
#define NLAYERS 3
#define NSUBT 2
#define OUTDIM 128

// batched CSR layout: 5 segments concatenated
// seg0: edges by dst (n=100000) base 0
// seg1: s0 by col (n=20000)  base 100000
// seg2: s0 by row (n=100000) base 120000
// seg3: s1 by col (n=20000)  base 220000
// seg4: s1 by row (n=100000) base 240000
#define CSR_R 340000
#define CSR_E 1400000
#define NBLK_SCAN 333
#define B_S0C 100000
#define B_S0R 120000
#define B_S1C 220000
#define B_S1R 240000

// ---------------- persistent scratch ----------------------------------------
__device__ float g_x   [N_NODES * HDIM];
__device__ float g_agg [N_NODES * HDIM];
__device__ float g_h   [N_NODES * H2DIM];
__device__ float g_msg [N_NODES * HDIM];
__device__ float g_sx  [NSUB * HDIM];
__device__ float g_sxh [NSUB * H2DIM];
__device__ float g_sx2 [NSUB * HDIM];
__device__ float g_sum  [H2DIM];
__device__ float g_sumsq[H2DIM];
__device__ float g_scale[H2DIM];
__device__ float g_shift[H2DIM];
#define W_TOTAL 1048576
__device__ __nv_bfloat16 g_whi[W_TOTAL];
__device__ __nv_bfloat16 g_wlo[W_TOTAL];
// batched CSR (counts are zero at kernel_launch entry; restored each run)
__device__ int g_cnt2  [CSR_R];
__device__ int g_cursor2[CSR_R];
__device__ int g_offs  [CSR_R + 1];
__device__ int g_part  [NBLK_SCAN + 1];
__device__ int g_csr   [CSR_E];

// ---------------- batched CSR build ------------------------------------------
__global__ void k_zeroi(int* __restrict__ p, int n) {
    int i = blockIdx.x * blockDim.x + threadIdx.x;
    if (i < n) p[i] = 0;
}
// decode global edge id -> (cnt index, stored value)
__device__ __forceinline__ void edge_decode(int e, const int* __restrict__ edge,
                                            const int* __restrict__ se0,
                                            const int* __restrict__ se1,
                                            int& d, int& s) {
    if (e < N_EDGES) { d = __ldg(edge + N_EDGES + e); s = __ldg(edge + e); return; }
    e -= N_EDGES;
    if (e < ESUB) { d = B_S0C + __ldg(se0 + ESUB + e); s = __ldg(se0 + e); return; }
    e -= ESUB;
    if (e < ESUB) { d = B_S0R + __ldg(se0 + e); s = __ldg(se0 + ESUB + e); return; }
    e -= ESUB;
    if (e < ESUB) { d = B_S1C + __ldg(se1 + ESUB + e); s = __ldg(se1 + e); return; }
    e -= ESUB;
    d = B_S1R + __ldg(se1 + e); s = __ldg(se1 + ESUB + e);
}
__global__ void k_hist_all(const int* __restrict__ edge, const int* __restrict__ se0,
                           const int* __restrict__ se1, int* __restrict__ cnt) {
    int e = blockIdx.x * blockDim.x + threadIdx.x;
    if (e >= CSR_E) return;
    int d, s;
    edge_decode(e, edge, se0, se1, d, s);
    atomicAdd(&cnt[d], 1);
}
__global__ void k_fill_all(const int* __restrict__ edge, const int* __restrict__ se0,
                           const int* __restrict__ se1, int* __restrict__ cursor,
                           int* __restrict__ csr) {
    int e = blockIdx.x * blockDim.x + threadIdx.x;
    if (e >= CSR_E) return;
    int d, s;
    edge_decode(e, edge, se0, se1, d, s);
    int pos = atomicAdd(&cursor[d], 1);
    csr[pos] = s;
}
// block-wide exclusive scan of v across 1024 threads; returns exclusive prefix
__device__ __forceinline__ int block_excl_scan(int v) {
    __shared__ int ws[32];
    int lane = threadIdx.x & 31, w = threadIdx.x >> 5;
    int x = v;
#pragma unroll
    for (int d = 1; d < 32; d <<= 1) {
        int y = __shfl_up_sync(0xFFFFFFFFu, x, d);
        if (lane >= d) x += y;
    }
    if (lane == 31) ws[w] = x;
    __syncthreads();
    if (w == 0) {
        int s = ws[lane];
#pragma unroll
        for (int d = 1; d < 32; d <<= 1) {
            int y = __shfl_up_sync(0xFFFFFFFFu, s, d);
            if (lane >= d) s += y;
        }
        ws[lane] = s;
    }
    __syncthreads();
    int woff = (w > 0) ? ws[w - 1] : 0;
    return x - v + woff;
}
__global__ void k_scanA(const int* __restrict__ cnt, int* __restrict__ offs,
                        int* __restrict__ part) {
    int idx = blockIdx.x * 1024 + threadIdx.x;
    int v = (idx < CSR_R) ? cnt[idx] : 0;
    int excl = block_excl_scan(v);
    if (idx < CSR_R) offs[idx] = excl;
    if (threadIdx.x == 1023) part[blockIdx.x] = excl + v;
}
__global__ void k_scanB(int* __restrict__ part) {
    int i = threadIdx.x;
    int v = (i < NBLK_SCAN) ? part[i] : 0;
    int excl = block_excl_scan(v);
    __syncthreads();
    if (i < NBLK_SCAN) part[i] = excl;
    if (i == NBLK_SCAN - 1) part[NBLK_SCAN] = excl + v;
}
__global__ void k_scanC(int* __restrict__ offs, const int* __restrict__ part,
                        int* __restrict__ cursor) {
    int idx = blockIdx.x * 1024 + threadIdx.x;
    if (idx < CSR_R) {
        int o = offs[idx] + part[blockIdx.x];
        offs[idx] = o;
        cursor[idx] = o;
    } else if (idx == CSR_R) {
        offs[CSR_R] = part[NBLK_SCAN];
    }
}

// ---------------- gather (unroll-4 for MLP) ----------------------------------
template <int BASE>
__global__ void k_gather(float* __restrict__ out, const float* __restrict__ in,
                         const int* __restrict__ offs, const int* __restrict__ srcs,
                         const float* __restrict__ basex, const float* __restrict__ eps,
                         int layer, int nrows) {
    int node = blockIdx.x * 8 + (threadIdx.x >> 5);
    if (node >= nrows) return;
    int lane4 = (threadIdx.x & 31) * 4;
    int b = __ldg(offs + node), e = __ldg(offs + node + 1);
    float4 acc;
    if (BASE == 1) {
        float cf = 1.0f + __ldg(eps + layer);
        float4 v = *reinterpret_cast<const float4*>(basex + (size_t)node * HDIM + lane4);
        acc = make_float4(cf * v.x, cf * v.y, cf * v.z, cf * v.w);
    } else {
        acc = make_float4(0.f, 0.f, 0.f, 0.f);
    }
    int j = b;
    for (; j + 4 <= e; j += 4) {
        int s0 = __ldg(srcs + j + 0), s1 = __ldg(srcs + j + 1);
        int s2 = __ldg(srcs + j + 2), s3 = __ldg(srcs + j + 3);
        float4 v0 = *reinterpret_cast<const float4*>(in + (size_t)s0 * HDIM + lane4);
        float4 v1 = *reinterpret_cast<const float4*>(in + (size_t)s1 * HDIM + lane4);
        float4 v2 = *reinterpret_cast<const float4*>(in + (size_t)s2 * HDIM + lane4);
        float4 v3 = *reinterpret_cast<const float4*>(in + (size_t)s3 * HDIM + lane4);
        acc.x += (v0.x + v1.x) + (v2.x + v3.x);
        acc.y += (v0.y + v1.y) + (v2.y + v3.y);
        acc.z += (v0.z + v1.z) + (v2.z + v3.z);
        acc.w += (v0.w + v1.w) + (v2.w + v3.w);
    }
    for (; j < e; j++) {
        int s = __ldg(srcs + j);
        float4 v = *reinterpret_cast<const float4*>(in + (size_t)s * HDIM + lane4);
        acc.x += v.x; acc.y += v.y; acc.z += v.z; acc.w += v.w;
    }
    *reinterpret_cast<float4*>(out + (size_t)node * HDIM + lane4) = acc;
}

// ---------------- BN stats ----------------------------------------------------
__global__ void k_zero_stats() {
    g_sum[threadIdx.x] = 0.f;
    g_sumsq[threadIdx.x] = 0.f;
}
__global__ void k_colstats(const float* __restrict__ h, int M) {
    __shared__ float bs[4][H2DIM];
    __shared__ float bss[4][H2DIM];
    int t = threadIdx.x;
    int c4 = (t & 63) * 4;
    int rs = t >> 6;
    float4 s = make_float4(0.f, 0.f, 0.f, 0.f);
    float4 ss = make_float4(0.f, 0.f, 0.f, 0.f);
    for (int r = blockIdx.x * 4 + rs; r < M; r += gridDim.x * 4) {
        float4 v = *reinterpret_cast<const float4*>(h + (size_t)r * H2DIM + c4);
        s.x += v.x; s.y += v.y; s.z += v.z; s.w += v.w;
        ss.x += v.x * v.x; ss.y += v.y * v.y; ss.z += v.z * v.z; ss.w += v.w * v.w;
    }
    *reinterpret_cast<float4*>(&bs[rs][c4]) = s;
    *reinterpret_cast<float4*>(&bss[rs][c4]) = ss;
    __syncthreads();
    if (rs == 0) {
#pragma unroll
        for (int j = 1; j < 4; j++) {
            float4 a = *reinterpret_cast<float4*>(&bs[j][c4]);
            float4 b = *reinterpret_cast<float4*>(&bss[j][c4]);
            s.x += a.x; s.y += a.y; s.z += a.z; s.w += a.w;
            ss.x += b.x; ss.y += b.y; ss.z += b.z; ss.w += b.w;
        }
        atomicAdd(&g_sum[c4 + 0], s.x); atomicAdd(&g_sum[c4 + 1], s.y);
        atomicAdd(&g_sum[c4 + 2], s.z); atomicAdd(&g_sum[c4 + 3], s.w);
        atomicAdd(&g_sumsq[c4 + 0], ss.x); atomicAdd(&g_sumsq[c4 + 1], ss.y);
        atomicAdd(&g_sumsq[c4 + 2], ss.z); atomicAdd(&g_sumsq[c4 + 3], ss.w);
    }
}
__global__ void k_bnfin(const float* __restrict__ gamma, const float* __restrict__ beta,
                        float invM) {
    int c = threadIdx.x;
    float mean = g_sum[c] * invM;
    float var  = g_sumsq[c] * invM - mean * mean;
    float sc   = __ldg(gamma + c) * rsqrtf(var + 1e-5f);
    g_scale[c] = sc;
    g_shift[c] = __ldg(beta + c) - mean * sc;
}
__global__ void k_prep(const float* __restrict__ W, int K, int Nw, int cnt,
                       __nv_bfloat16* __restrict__ hi, __nv_bfloat16* __restrict__ lo) {
    int i = blockIdx.x * blockDim.x + threadIdx.x;
    int per = K * Nw;
    if (i >= cnt * per) return;
    int m = i / per, r = i % per;
    int k = r / Nw, n = r % Nw;
    float w = W[i];
    __nv_bfloat16 h = __float2bfloat16(w);
    float res = w - __bfloat162float(h);
    size_t o = (size_t)m * per + (size_t)n * K + k;
    hi[o] = h;
    lo[o] = __float2bfloat16(res);
}

// ---------------- mma.sync helpers ------------------------------------------
__device__ __forceinline__ uint32_t smem_u32(const void* p) {
    uint32_t a;
    asm("{ .reg .u64 t; cvta.to.shared.u64 t, %1; cvt.u32.u64 %0, t; }" : "=r"(a) : "l"(p));
    return a;
}
__device__ __forceinline__ void ldsm_x4(uint32_t* r, uint32_t addr) {
    asm volatile("ldmatrix.sync.aligned.m8n8.x4.shared.b16 {%0,%1,%2,%3}, [%4];"
                 : "=r"(r[0]), "=r"(r[1]), "=r"(r[2]), "=r"(r[3]) : "r"(addr));
}
__device__ __forceinline__ void mma16816(float* d, const uint32_t* a, uint32_t b0, uint32_t b1) {
    asm volatile(
        "mma.sync.aligned.m16n8k16.row.col.f32.bf16.bf16.f32 "
        "{%0,%1,%2,%3}, {%4,%5,%6,%7}, {%8,%9}, {%0,%1,%2,%3};"
        : "+f"(d[0]), "+f"(d[1]), "+f"(d[2]), "+f"(d[3])
        : "r"(a[0]), "r"(a[1]), "r"(a[2]), "r"(a[3]), "r"(b0), "r"(b1));
}
__device__ __forceinline__ void cp_async16(uint32_t dst, const void* src) {
    asm volatile("cp.async.cg.shared.global [%0], [%1], 16;" :: "r"(dst), "l"(src));
}

// ---------------- mma.sync split-bf16 GEMM ----------------------------------
#define S_AHI 0
#define S_ALO 16384
#define S_BHI 32768
#define S_BLO 49152
#define GEMM_SMEM 65536

template <int AOP, int EOP>
__global__ __launch_bounds__(256, 2) void k_gemm_mma(
    const float* __restrict__ A, const __nv_bfloat16* __restrict__ Bhi,
    const __nv_bfloat16* __restrict__ Blo, const float* __restrict__ bias,
    float* __restrict__ C, int M, int K, int Nw,
    const float* __restrict__ scale, const float* __restrict__ shift) {
    extern __shared__ char smem[];
    const uint32_t sbase = smem_u32(smem);
    const int tid = threadIdx.x;
    const int wid = tid >> 5;
    const int lane = tid & 31;
    const int row0 = blockIdx.y * 128;
    const int col0 = blockIdx.x * 128;
    const int wm = (wid & 3) * 32;
    const int wn = (wid >> 2) * 64;

    float acc[2][8][4];
#pragma unroll
    for (int i = 0; i < 2; i++)
#pragma unroll
        for (int j = 0; j < 8; j++)
#pragma unroll
            for (int q = 0; q < 4; q++) acc[i][j][q] = 0.f;

    for (int chunk = 0; chunk < K; chunk += 64) {
#pragma unroll
        for (int it = 0; it < 4; it++) {
            int task = tid + it * 256;
            int r = task >> 3;
            int c16 = task & 7;
            uint32_t soff = (uint32_t)r * 128u + (uint32_t)((c16 ^ (r & 7)) << 4);
            const __nv_bfloat16* bh = Bhi + (size_t)(col0 + r) * K + chunk + c16 * 8;
            const __nv_bfloat16* bl = Blo + (size_t)(col0 + r) * K + chunk + c16 * 8;
            cp_async16(sbase + S_BHI + soff, bh);
            cp_async16(sbase + S_BLO + soff, bl);
        }
        asm volatile("cp.async.commit_group;" ::: "memory");

#pragma unroll
        for (int it = 0; it < 4; it++) {
            int task = tid + it * 256;
            int r = task >> 3;
            int c16 = task & 7;
            uint32_t soff = (uint32_t)r * 128u + (uint32_t)((c16 ^ (r & 7)) << 4);
            float4 v0 = make_float4(0.f, 0.f, 0.f, 0.f), v1 = v0;
            if (row0 + r < M) {
                const float* ap = A + (size_t)(row0 + r) * K + chunk + c16 * 8;
                v0 = *reinterpret_cast<const float4*>(ap);
                v1 = *reinterpret_cast<const float4*>(ap + 4);
                if (AOP == 1) {
                    int gk = chunk + c16 * 8;
                    float4 sc0 = *reinterpret_cast<const float4*>(scale + gk);
                    float4 sc1 = *reinterpret_cast<const float4*>(scale + gk + 4);
                    float4 sh0 = *reinterpret_cast<const float4*>(shift + gk);
                    float4 sh1 = *reinterpret_cast<const float4*>(shift + gk + 4);
                    v0.x = fmaxf(fmaf(v0.x, sc0.x, sh0.x), 0.f);
                    v0.y = fmaxf(fmaf(v0.y, sc0.y, sh0.y), 0.f);
                    v0.z = fmaxf(fmaf(v0.z, sc0.z, sh0.z), 0.f);
                    v0.w = fmaxf(fmaf(v0.w, sc0.w, sh0.w), 0.f);
                    v1.x = fmaxf(fmaf(v1.x, sc1.x, sh1.x), 0.f);
                    v1.y = fmaxf(fmaf(v1.y, sc1.y, sh1.y), 0.f);
                    v1.z = fmaxf(fmaf(v1.z, sc1.z, sh1.z), 0.f);
                    v1.w = fmaxf(fmaf(v1.w, sc1.w, sh1.w), 0.f);
                }
            }
            __nv_bfloat162 h01 = __float22bfloat162_rn(make_float2(v0.x, v0.y));
            __nv_bfloat162 h23 = __float22bfloat162_rn(make_float2(v0.z, v0.w));
            __nv_bfloat162 h45 = __float22bfloat162_rn(make_float2(v1.x, v1.y));
            __nv_bfloat162 h67 = __float22bfloat162_rn(make_float2(v1.z, v1.w));
            float2 f01 = __bfloat1622float2(h01), f23 = __bfloat1622float2(h23);
            float2 f45 = __bfloat1622float2(h45), f67 = __bfloat1622float2(h67);
            __nv_bfloat162 l01 = __float22bfloat162_rn(make_float2(v0.x - f01.x, v0.y - f01.y));
            __nv_bfloat162 l23 = __float22bfloat162_rn(make_float2(v0.z - f23.x, v0.w - f23.y));
            __nv_bfloat162 l45 = __float22bfloat162_rn(make_float2(v1.x - f45.x, v1.y - f45.y));
            __nv_bfloat162 l67 = __float22bfloat162_rn(make_float2(v1.z - f67.x, v1.w - f67.y));
            uint4 hp, lp;
            hp.x = *(uint32_t*)&h01; hp.y = *(uint32_t*)&h23;
            hp.z = *(uint32_t*)&h45; hp.w = *(uint32_t*)&h67;
            lp.x = *(uint32_t*)&l01; lp.y = *(uint32_t*)&l23;
            lp.z = *(uint32_t*)&l45; lp.w = *(uint32_t*)&l67;
            *reinterpret_cast<uint4*>(smem + S_AHI + soff) = hp;
            *reinterpret_cast<uint4*>(smem + S_ALO + soff) = lp;
        }
        asm volatile("cp.async.wait_group 0;" ::: "memory");
        __syncthreads();

#pragma unroll
        for (int ks = 0; ks < 4; ks++) {
            uint32_t ahi[2][4], alo[2][4];
#pragma unroll
            for (int ms = 0; ms < 2; ms++) {
                int r = wm + ms * 16 + (lane & 15);
                int c16 = ks * 2 + (lane >> 4);
                uint32_t off = (uint32_t)r * 128u + (uint32_t)(((c16 ^ (r & 7))) << 4);
                ldsm_x4(ahi[ms], sbase + S_AHI + off);
                ldsm_x4(alo[ms], sbase + S_ALO + off);
            }
#pragma unroll
            for (int p = 0; p < 4; p++) {
                int n = wn + p * 16 + ((lane >> 4) << 3) + (lane & 7);
                int c16 = ks * 2 + ((lane >> 3) & 1);
                uint32_t off = (uint32_t)n * 128u + (uint32_t)(((c16 ^ (n & 7))) << 4);
                uint32_t bh[4], bl[4];
                ldsm_x4(bh, sbase + S_BHI + off);
                ldsm_x4(bl, sbase + S_BLO + off);
#pragma unroll
                for (int ms = 0; ms < 2; ms++) {
                    mma16816(acc[ms][2 * p],     ahi[ms], bh[0], bh[1]);
                    mma16816(acc[ms][2 * p + 1], ahi[ms], bh[2], bh[3]);
                    mma16816(acc[ms][2 * p],     alo[ms], bh[0], bh[1]);
                    mma16816(acc[ms][2 * p + 1], alo[ms], bh[2], bh[3]);
                    mma16816(acc[ms][2 * p],     ahi[ms], bl[0], bl[1]);
                    mma16816(acc[ms][2 * p + 1], ahi[ms], bl[2], bl[3]);
                }
            }
        }
        __syncthreads();
    }

#pragma unroll
    for (int ms = 0; ms < 2; ms++) {
#pragma unroll
        for (int nt = 0; nt < 8; nt++) {
            int c = col0 + wn + nt * 8 + (lane & 3) * 2;
            float2 bi = *reinterpret_cast<const float2*>(bias + c);
            int r = row0 + wm + ms * 16 + (lane >> 2);
#pragma unroll
            for (int half = 0; half < 2; half++) {
                int rr = r + half * 8;
                if (rr >= M) continue;
                float2 v;
                v.x = acc[ms][nt][2 * half + 0] + bi.x;
                v.y = acc[ms][nt][2 * half + 1] + bi.y;
                if (EOP == 1) { v.x = fmaxf(v.x, 0.f); v.y = fmaxf(v.y, 0.f); }
                float* cp = C + (size_t)rr * Nw + c;
                if (EOP == 2) {
                    float2 o = *reinterpret_cast<const float2*>(cp);
                    v.x += o.x; v.y += o.y;
                }
                *reinterpret_cast<float2*>(cp) = v;
            }
        }
    }
}

// ---------------- host orchestration ---------------------------------------
extern "C" void kernel_launch(void* const* d_in, const int* in_sizes, int n_in,
                              void* d_out, int out_size) {
    const float* x_in    = (const float*)d_in[0];
    const int*   edge    = (const int*)d_in[1];
    const int*   se0     = (const int*)d_in[2];
    const int*   se1     = (const int*)d_in[3];
    const float* msg_w1  = (const float*)d_in[4];
    const float* msg_b1  = (const float*)d_in[5];
    const float* bn_g    = (const float*)d_in[6];
    const float* bn_b    = (const float*)d_in[7];
    const float* msg_w2  = (const float*)d_in[8];
    const float* msg_b2  = (const float*)d_in[9];
    const float* eps_gin = (const float*)d_in[10];
    const float* n2s_w1  = (const float*)d_in[11];
    const float* n2s_b1  = (const float*)d_in[12];
    const float* n2s_w2  = (const float*)d_in[13];
    const float* n2s_b2  = (const float*)d_in[14];
    const float* s2n_w1  = (const float*)d_in[15];
    const float* s2n_b1  = (const float*)d_in[16];
    const float* s2n_w2  = (const float*)d_in[17];
    const float* s2n_b2  = (const float*)d_in[18];
    const float* out_w1  = (const float*)d_in[19];
    const float* out_b1  = (const float*)d_in[20];
    const float* out_w2  = (const float*)d_in[21];
    const float* out_b2  = (const float*)d_in[22];

    float *xb, *aggb, *hb, *msgb, *sxb, *sxhb, *sx2b, *scaleb, *shiftb;
    __nv_bfloat16 *whi, *wlo;
    int *cnt2, *cursor2, *offsb, *partb, *csrb;
    cudaGetSymbolAddress((void**)&xb,    g_x);
    cudaGetSymbolAddress((void**)&aggb,  g_agg);
    cudaGetSymbolAddress((void**)&hb,    g_h);
    cudaGetSymbolAddress((void**)&msgb,  g_msg);
    cudaGetSymbolAddress((void**)&sxb,   g_sx);
    cudaGetSymbolAddress((void**)&sxhb,  g_sxh);
    cudaGetSymbolAddress((void**)&sx2b,  g_sx2);
    cudaGetSymbolAddress((void**)&scaleb, g_scale);
    cudaGetSymbolAddress((void**)&shiftb, g_shift);
    cudaGetSymbolAddress((void**)&whi,   g_whi);
    cudaGetSymbolAddress((void**)&wlo,   g_wlo);
    cudaGetSymbolAddress((void**)&cnt2,    g_cnt2);
    cudaGetSymbolAddress((void**)&cursor2, g_cursor2);
    cudaGetSymbolAddress((void**)&offsb,   g_offs);
    cudaGetSymbolAddress((void**)&partb,   g_part);
    cudaGetSymbolAddress((void**)&csrb,    g_csr);

    cudaFuncSetAttribute(k_gemm_mma<0, 0>, cudaFuncAttributeMaxDynamicSharedMemorySize, GEMM_SMEM);
    cudaFuncSetAttribute(k_gemm_mma<1, 0>, cudaFuncAttributeMaxDynamicSharedMemorySize, GEMM_SMEM);
    cudaFuncSetAttribute(k_gemm_mma<0, 1>, cudaFuncAttributeMaxDynamicSharedMemorySize, GEMM_SMEM);
    cudaFuncSetAttribute(k_gemm_mma<0, 2>, cudaFuncAttributeMaxDynamicSharedMemorySize, GEMM_SMEM);

    const size_t O_MSG1 = 0,       O_MSG2 = 98304,  O_N2S1 = 196608, O_N2S2 = 393216;
    const size_t O_S2N1 = 589824,  O_S2N2 = 786432, O_OUT1 = 983040, O_OUT2 = 1015808;
    const int PB = 256;
    auto prep = [&](const float* W, int K, int Nw, int cntw, size_t off) {
        int tot = cntw * K * Nw;
        k_prep<<<(tot + PB - 1) / PB, PB>>>(W, K, Nw, cntw, whi + off, wlo + off);
    };

    const int gGN = (N_NODES + 7) / 8;
    const int gGS = (NSUB + 7) / 8;
    const int EB = (CSR_E + 255) / 256;

    // --- launches 0-4: batched CSR build (cnt2 is zero at entry; invariant
    //     restored by the cleanup zero below). Launch 5: GIN gather (ncu -s 5). ---
    k_hist_all<<<EB, 256>>>(edge, se0, se1, cnt2);
    k_scanA<<<NBLK_SCAN, 1024>>>(cnt2, offsb, partb);
    k_scanB<<<1, 1024>>>(partb);
    k_scanC<<<NBLK_SCAN, 1024>>>(offsb, partb, cursor2);
    k_fill_all<<<EB, 256>>>(edge, se0, se1, cursor2, csrb);
    k_gather<1><<<gGN, 256>>>(aggb, x_in, offsb, csrb, x_in, eps_gin, 0, N_NODES);
    // restore counts-zero invariant for the next execution of this graph
    k_zeroi<<<(CSR_R + 255) / 256, 256>>>(cnt2, CSR_R);

    // weight preps
    prep(msg_w1, HDIM, H2DIM, 3, O_MSG1);
    prep(msg_w2, H2DIM, HDIM, 3, O_MSG2);
    prep(n2s_w1, HDIM, H2DIM, 6, O_N2S1);
    prep(n2s_w2, H2DIM, HDIM, 6, O_N2S2);
    prep(s2n_w1, HDIM, H2DIM, 6, O_S2N1);
    prep(s2n_w2, H2DIM, HDIM, 6, O_S2N2);
    prep(out_w1, HDIM, H2DIM, 1, O_OUT1);
    prep(out_w2, H2DIM, HDIM, 1, O_OUT2);

    dim3 gN2(2, (N_NODES + 127) / 128);
    dim3 gN1(1, (N_NODES + 127) / 128);
    dim3 gS2(2, (NSUB + 127) / 128);
    dim3 gS1(1, (NSUB + 127) / 128);

    for (int i = 0; i < NLAYERS; i++) {
        if (i > 0)
            k_gather<1><<<gGN, 256>>>(aggb, xb, offsb, csrb, xb, eps_gin, i, N_NODES);

        k_gemm_mma<0, 0><<<gN2, 256, GEMM_SMEM>>>(
            aggb, whi + O_MSG1 + (size_t)i * HDIM * H2DIM, wlo + O_MSG1 + (size_t)i * HDIM * H2DIM,
            msg_b1 + (size_t)i * H2DIM, hb, N_NODES, HDIM, H2DIM, nullptr, nullptr);
        k_zero_stats<<<1, 256>>>();
        k_colstats<<<296, 256>>>(hb, N_NODES);
        k_bnfin<<<1, 256>>>(bn_g + (size_t)i * H2DIM, bn_b + (size_t)i * H2DIM,
                            1.0f / (float)N_NODES);
        k_gemm_mma<1, 0><<<gN1, 256, GEMM_SMEM>>>(
            hb, whi + O_MSG2 + (size_t)i * H2DIM * HDIM, wlo + O_MSG2 + (size_t)i * H2DIM * HDIM,
            msg_b2 + (size_t)i * HDIM, xb, N_NODES, H2DIM, HDIM, scaleb, shiftb);

        for (int s = 0; s < NSUBT; s++) {
            const int* offc = offsb + ((s == 0) ? B_S0C : B_S1C);
            const int* offr = offsb + ((s == 0) ? B_S0R : B_S1R);
            const size_t widx = (size_t)i * NSUBT + s;

            k_gather<0><<<gGS, 256>>>(sxb, xb, offc, csrb, nullptr, nullptr, 0, NSUB);

            k_gemm_mma<0, 1><<<gS2, 256, GEMM_SMEM>>>(
                sxb, whi + O_N2S1 + widx * HDIM * H2DIM, wlo + O_N2S1 + widx * HDIM * H2DIM,
                n2s_b1 + widx * H2DIM, sxhb, NSUB, HDIM, H2DIM, nullptr, nullptr);
            k_gemm_mma<0, 0><<<gS1, 256, GEMM_SMEM>>>(
                sxhb, whi + O_N2S2 + widx * H2DIM * HDIM, wlo + O_N2S2 + widx * H2DIM * HDIM,
                n2s_b2 + widx * HDIM, sx2b, NSUB, H2DIM, HDIM, nullptr, nullptr);

            k_gather<0><<<gGN, 256>>>(msgb, sx2b, offr, csrb, nullptr, nullptr, 0, N_NODES);

            k_gemm_mma<0, 1><<<gN2, 256, GEMM_SMEM>>>(
                msgb, whi + O_S2N1 + widx * HDIM * H2DIM, wlo + O_S2N1 + widx * HDIM * H2DIM,
                s2n_b1 + widx * H2DIM, hb, N_NODES, HDIM, H2DIM, nullptr, nullptr);
            k_gemm_mma<0, 2><<<gN1, 256, GEMM_SMEM>>>(
                hb, whi + O_S2N2 + widx * H2DIM * HDIM, wlo + O_S2N2 + widx * H2DIM * HDIM,
                s2n_b2 + widx * HDIM, xb, N_NODES, H2DIM, HDIM, nullptr, nullptr);
        }
    }

    k_gemm_mma<0, 1><<<gN2, 256, GEMM_SMEM>>>(
        xb, whi + O_OUT1, wlo + O_OUT1, out_b1, hb, N_NODES, HDIM, H2DIM, nullptr, nullptr);
    k_gemm_mma<0, 0><<<gN1, 256, GEMM_SMEM>>>(
        hb, whi + O_OUT2, wlo + O_OUT2, out_b2, (float*)d_out,
        N_NODES, H2DIM, OUTDIM, nullptr, nullptr);
}

// round 7
// speedup vs baseline: 1.8711x; 1.0332x over previous
#include <cuda_runtime.h>
#include <cuda_bf16.h>
#include <cstdint>

#define N_NODES 100000
#define HDIM 128
#define H2DIM 256
#define N_EDGES 600000
#define NSUB 20000
#define ESUB 200000
#define NLAYERS 3
#define NSUBT 2
#define OUTDIM 128

#define CSR_R 340000
#define CSR_E 1400000
#define NBLK_SCAN 333
#define B_S0C 100000
#define B_S0R 120000
#define B_S1C 220000
#define B_S1R 240000

// ---------------- persistent scratch ----------------------------------------
__device__ float g_x   [N_NODES * HDIM];
__device__ float g_agg [N_NODES * HDIM];
__device__ float g_h   [N_NODES * H2DIM];
__device__ float g_msg [N_NODES * HDIM];
__device__ float g_sx  [NSUB * HDIM];
__device__ float g_sxh [NSUB * H2DIM];
__device__ float g_sx2 [NSUB * HDIM];
__device__ float g_sum  [H2DIM];
__device__ float g_sumsq[H2DIM];
__device__ float g_scale[H2DIM];
__device__ float g_shift[H2DIM];
#define W_TOTAL 1048576
__device__ __nv_bfloat16 g_whi[W_TOTAL];
__device__ __nv_bfloat16 g_wlo[W_TOTAL];
__device__ int g_cnt2  [CSR_R];
__device__ int g_cursor2[CSR_R];
__device__ int g_offs  [CSR_R + 1];
__device__ int g_part  [NBLK_SCAN + 1];
__device__ int g_csr   [CSR_E];

// ---------------- batched CSR build ------------------------------------------
__global__ void k_zeroi(int* __restrict__ p, int n) {
    int i = blockIdx.x * blockDim.x + threadIdx.x;
    if (i < n) p[i] = 0;
}
__device__ __forceinline__ void edge_decode(int e, const int* __restrict__ edge,
                                            const int* __restrict__ se0,
                                            const int* __restrict__ se1,
                                            int& d, int& s) {
    if (e < N_EDGES) { d = __ldg(edge + N_EDGES + e); s = __ldg(edge + e); return; }
    e -= N_EDGES;
    if (e < ESUB) { d = B_S0C + __ldg(se0 + ESUB + e); s = __ldg(se0 + e); return; }
    e -= ESUB;
    if (e < ESUB) { d = B_S0R + __ldg(se0 + e); s = __ldg(se0 + ESUB + e); return; }
    e -= ESUB;
    if (e < ESUB) { d = B_S1C + __ldg(se1 + ESUB + e); s = __ldg(se1 + e); return; }
    e -= ESUB;
    d = B_S1R + __ldg(se1 + e); s = __ldg(se1 + ESUB + e);
}
__global__ void k_hist_all(const int* __restrict__ edge, const int* __restrict__ se0,
                           const int* __restrict__ se1, int* __restrict__ cnt) {
    int e = blockIdx.x * blockDim.x + threadIdx.x;
    if (e >= CSR_E) return;
    int d, s;
    edge_decode(e, edge, se0, se1, d, s);
    atomicAdd(&cnt[d], 1);
}
__global__ void k_fill_all(const int* __restrict__ edge, const int* __restrict__ se0,
                           const int* __restrict__ se1, int* __restrict__ cursor,
                           int* __restrict__ csr) {
    int e = blockIdx.x * blockDim.x + threadIdx.x;
    if (e >= CSR_E) return;
    int d, s;
    edge_decode(e, edge, se0, se1, d, s);
    int pos = atomicAdd(&cursor[d], 1);
    csr[pos] = s;
}
__device__ __forceinline__ int block_excl_scan(int v) {
    __shared__ int ws[32];
    int lane = threadIdx.x & 31, w = threadIdx.x >> 5;
    int x = v;
#pragma unroll
    for (int d = 1; d < 32; d <<= 1) {
        int y = __shfl_up_sync(0xFFFFFFFFu, x, d);
        if (lane >= d) x += y;
    }
    if (lane == 31) ws[w] = x;
    __syncthreads();
    if (w == 0) {
        int s = ws[lane];
#pragma unroll
        for (int d = 1; d < 32; d <<= 1) {
            int y = __shfl_up_sync(0xFFFFFFFFu, s, d);
            if (lane >= d) s += y;
        }
        ws[lane] = s;
    }
    __syncthreads();
    int woff = (w > 0) ? ws[w - 1] : 0;
    return x - v + woff;
}
__global__ void k_scanA(const int* __restrict__ cnt, int* __restrict__ offs,
                        int* __restrict__ part) {
    int idx = blockIdx.x * 1024 + threadIdx.x;
    int v = (idx < CSR_R) ? cnt[idx] : 0;
    int excl = block_excl_scan(v);
    if (idx < CSR_R) offs[idx] = excl;
    if (threadIdx.x == 1023) part[blockIdx.x] = excl + v;
}
__global__ void k_scanB(int* __restrict__ part) {
    int i = threadIdx.x;
    int v = (i < NBLK_SCAN) ? part[i] : 0;
    int excl = block_excl_scan(v);
    __syncthreads();
    if (i < NBLK_SCAN) part[i] = excl;
    if (i == NBLK_SCAN - 1) part[NBLK_SCAN] = excl + v;
}
__global__ void k_scanC(int* __restrict__ offs, const int* __restrict__ part,
                        int* __restrict__ cursor) {
    int idx = blockIdx.x * 1024 + threadIdx.x;
    if (idx < CSR_R) {
        int o = offs[idx] + part[blockIdx.x];
        offs[idx] = o;
        cursor[idx] = o;
    } else if (idx == CSR_R) {
        offs[CSR_R] = part[NBLK_SCAN];
    }
}

// ---------------- gather ------------------------------------------------------
template <int BASE>
__global__ void k_gather(float* __restrict__ out, const float* __restrict__ in,
                         const int* __restrict__ offs, const int* __restrict__ srcs,
                         const float* __restrict__ basex, const float* __restrict__ eps,
                         int layer, int nrows) {
    int node = blockIdx.x * 8 + (threadIdx.x >> 5);
    if (node >= nrows) return;
    int lane4 = (threadIdx.x & 31) * 4;
    int b = __ldg(offs + node), e = __ldg(offs + node + 1);
    float4 acc;
    if (BASE == 1) {
        float cf = 1.0f + __ldg(eps + layer);
        float4 v = *reinterpret_cast<const float4*>(basex + (size_t)node * HDIM + lane4);
        acc = make_float4(cf * v.x, cf * v.y, cf * v.z, cf * v.w);
    } else {
        acc = make_float4(0.f, 0.f, 0.f, 0.f);
    }
    int j = b;
    for (; j + 4 <= e; j += 4) {
        int s0 = __ldg(srcs + j + 0), s1 = __ldg(srcs + j + 1);
        int s2 = __ldg(srcs + j + 2), s3 = __ldg(srcs + j + 3);
        float4 v0 = *reinterpret_cast<const float4*>(in + (size_t)s0 * HDIM + lane4);
        float4 v1 = *reinterpret_cast<const float4*>(in + (size_t)s1 * HDIM + lane4);
        float4 v2 = *reinterpret_cast<const float4*>(in + (size_t)s2 * HDIM + lane4);
        float4 v3 = *reinterpret_cast<const float4*>(in + (size_t)s3 * HDIM + lane4);
        acc.x += (v0.x + v1.x) + (v2.x + v3.x);
        acc.y += (v0.y + v1.y) + (v2.y + v3.y);
        acc.z += (v0.z + v1.z) + (v2.z + v3.z);
        acc.w += (v0.w + v1.w) + (v2.w + v3.w);
    }
    for (; j < e; j++) {
        int s = __ldg(srcs + j);
        float4 v = *reinterpret_cast<const float4*>(in + (size_t)s * HDIM + lane4);
        acc.x += v.x; acc.y += v.y; acc.z += v.z; acc.w += v.w;
    }
    *reinterpret_cast<float4*>(out + (size_t)node * HDIM + lane4) = acc;
}

// ---------------- BN finalize (also resets accumulators) ----------------------
__global__ void k_zero_stats() {
    g_sum[threadIdx.x] = 0.f;
    g_sumsq[threadIdx.x] = 0.f;
}
__global__ void k_bnfin(const float* __restrict__ gamma, const float* __restrict__ beta,
                        float invM) {
    int c = threadIdx.x;
    float mean = g_sum[c] * invM;
    float var  = g_sumsq[c] * invM - mean * mean;
    float sc   = __ldg(gamma + c) * rsqrtf(var + 1e-5f);
    g_scale[c] = sc;
    g_shift[c] = __ldg(beta + c) - mean * sc;
    g_sum[c] = 0.f;     // reset for next layer / next replay
    g_sumsq[c] = 0.f;
}

// ---------------- single-launch weight prep (split + transpose) --------------
// dst layout matches O_* offsets; thread i handles global element i.
__global__ void k_prep_all(const float* __restrict__ w0, const float* __restrict__ w1,
                           const float* __restrict__ w2, const float* __restrict__ w3,
                           const float* __restrict__ w4, const float* __restrict__ w5,
                           const float* __restrict__ w6, const float* __restrict__ w7,
                           __nv_bfloat16* __restrict__ hi, __nv_bfloat16* __restrict__ lo) {
    int i = blockIdx.x * blockDim.x + threadIdx.x;
    if (i >= W_TOTAL) return;
    const float* src;
    int base, K, Nw;
    if      (i < 98304)   { src = w0; base = 0;       K = 128; Nw = 256; }
    else if (i < 196608)  { src = w1; base = 98304;   K = 256; Nw = 128; }
    else if (i < 393216)  { src = w2; base = 196608;  K = 128; Nw = 256; }
    else if (i < 589824)  { src = w3; base = 393216;  K = 256; Nw = 128; }
    else if (i < 786432)  { src = w4; base = 589824;  K = 128; Nw = 256; }
    else if (i < 983040)  { src = w5; base = 786432;  K = 256; Nw = 128; }
    else if (i < 1015808) { src = w6; base = 983040;  K = 128; Nw = 256; }
    else                  { src = w7; base = 1015808; K = 256; Nw = 128; }
    int local = i - base;
    int per = K * Nw;
    int m = local / per, r = local % per;
    int k = r / Nw, n = r % Nw;
    float w = __ldg(src + local);
    __nv_bfloat16 h = __float2bfloat16(w);
    float res = w - __bfloat162float(h);
    int o = base + m * per + n * K + k;
    hi[o] = h;
    lo[o] = __float2bfloat16(res);
}

// ---------------- mma.sync helpers ------------------------------------------
__device__ __forceinline__ uint32_t smem_u32(const void* p) {
    uint32_t a;
    asm("{ .reg .u64 t; cvta.to.shared.u64 t, %1; cvt.u32.u64 %0, t; }" : "=r"(a) : "l"(p));
    return a;
}
__device__ __forceinline__ void ldsm_x4(uint32_t* r, uint32_t addr) {
    asm volatile("ldmatrix.sync.aligned.m8n8.x4.shared.b16 {%0,%1,%2,%3}, [%4];"
                 : "=r"(r[0]), "=r"(r[1]), "=r"(r[2]), "=r"(r[3]) : "r"(addr));
}
__device__ __forceinline__ void mma16816(float* d, const uint32_t* a, uint32_t b0, uint32_t b1) {
    asm volatile(
        "mma.sync.aligned.m16n8k16.row.col.f32.bf16.bf16.f32 "
        "{%0,%1,%2,%3}, {%4,%5,%6,%7}, {%8,%9}, {%0,%1,%2,%3};"
        : "+f"(d[0]), "+f"(d[1]), "+f"(d[2]), "+f"(d[3])
        : "r"(a[0]), "r"(a[1]), "r"(a[2]), "r"(a[3]), "r"(b0), "r"(b1));
}
__device__ __forceinline__ void cp_async16(uint32_t dst, const void* src) {
    asm volatile("cp.async.cg.shared.global [%0], [%1], 16;" :: "r"(dst), "l"(src));
}

// ---------------- mma.sync split-bf16 GEMM ----------------------------------
#define S_AHI 0
#define S_ALO 16384
#define S_BHI 32768
#define S_BLO 49152
#define GEMM_SMEM 65536

template <int AOP, int EOP, int STATS>
__global__ __launch_bounds__(256, 2) void k_gemm_mma(
    const float* __restrict__ A, const __nv_bfloat16* __restrict__ Bhi,
    const __nv_bfloat16* __restrict__ Blo, const float* __restrict__ bias,
    float* __restrict__ C, int M, int K, int Nw,
    const float* __restrict__ scale, const float* __restrict__ shift) {
    extern __shared__ char smem[];
    const uint32_t sbase = smem_u32(smem);
    const int tid = threadIdx.x;
    const int wid = tid >> 5;
    const int lane = tid & 31;
    const int row0 = blockIdx.y * 128;
    const int col0 = blockIdx.x * 128;
    const int wm = (wid & 3) * 32;
    const int wn = (wid >> 2) * 64;

    float acc[2][8][4];
#pragma unroll
    for (int i = 0; i < 2; i++)
#pragma unroll
        for (int j = 0; j < 8; j++)
#pragma unroll
            for (int q = 0; q < 4; q++) acc[i][j][q] = 0.f;

    for (int chunk = 0; chunk < K; chunk += 64) {
#pragma unroll
        for (int it = 0; it < 4; it++) {
            int task = tid + it * 256;
            int r = task >> 3;
            int c16 = task & 7;
            uint32_t soff = (uint32_t)r * 128u + (uint32_t)((c16 ^ (r & 7)) << 4);
            const __nv_bfloat16* bh = Bhi + (size_t)(col0 + r) * K + chunk + c16 * 8;
            const __nv_bfloat16* bl = Blo + (size_t)(col0 + r) * K + chunk + c16 * 8;
            cp_async16(sbase + S_BHI + soff, bh);
            cp_async16(sbase + S_BLO + soff, bl);
        }
        asm volatile("cp.async.commit_group;" ::: "memory");

#pragma unroll
        for (int it = 0; it < 4; it++) {
            int task = tid + it * 256;
            int r = task >> 3;
            int c16 = task & 7;
            uint32_t soff = (uint32_t)r * 128u + (uint32_t)((c16 ^ (r & 7)) << 4);
            float4 v0 = make_float4(0.f, 0.f, 0.f, 0.f), v1 = v0;
            if (row0 + r < M) {
                const float* ap = A + (size_t)(row0 + r) * K + chunk + c16 * 8;
                v0 = *reinterpret_cast<const float4*>(ap);
                v1 = *reinterpret_cast<const float4*>(ap + 4);
                if (AOP == 1) {
                    int gk = chunk + c16 * 8;
                    float4 sc0 = *reinterpret_cast<const float4*>(scale + gk);
                    float4 sc1 = *reinterpret_cast<const float4*>(scale + gk + 4);
                    float4 sh0 = *reinterpret_cast<const float4*>(shift + gk);
                    float4 sh1 = *reinterpret_cast<const float4*>(shift + gk + 4);
                    v0.x = fmaxf(fmaf(v0.x, sc0.x, sh0.x), 0.f);
                    v0.y = fmaxf(fmaf(v0.y, sc0.y, sh0.y), 0.f);
                    v0.z = fmaxf(fmaf(v0.z, sc0.z, sh0.z), 0.f);
                    v0.w = fmaxf(fmaf(v0.w, sc0.w, sh0.w), 0.f);
                    v1.x = fmaxf(fmaf(v1.x, sc1.x, sh1.x), 0.f);
                    v1.y = fmaxf(fmaf(v1.y, sc1.y, sh1.y), 0.f);
                    v1.z = fmaxf(fmaf(v1.z, sc1.z, sh1.z), 0.f);
                    v1.w = fmaxf(fmaf(v1.w, sc1.w, sh1.w), 0.f);
                }
            }
            __nv_bfloat162 h01 = __float22bfloat162_rn(make_float2(v0.x, v0.y));
            __nv_bfloat162 h23 = __float22bfloat162_rn(make_float2(v0.z, v0.w));
            __nv_bfloat162 h45 = __float22bfloat162_rn(make_float2(v1.x, v1.y));
            __nv_bfloat162 h67 = __float22bfloat162_rn(make_float2(v1.z, v1.w));
            float2 f01 = __bfloat1622float2(h01), f23 = __bfloat1622float2(h23);
            float2 f45 = __bfloat1622float2(h45), f67 = __bfloat1622float2(h67);
            __nv_bfloat162 l01 = __float22bfloat162_rn(make_float2(v0.x - f01.x, v0.y - f01.y));
            __nv_bfloat162 l23 = __float22bfloat162_rn(make_float2(v0.z - f23.x, v0.w - f23.y));
            __nv_bfloat162 l45 = __float22bfloat162_rn(make_float2(v1.x - f45.x, v1.y - f45.y));
            __nv_bfloat162 l67 = __float22bfloat162_rn(make_float2(v1.z - f67.x, v1.w - f67.y));
            uint4 hp, lp;
            hp.x = *(uint32_t*)&h01; hp.y = *(uint32_t*)&h23;
            hp.z = *(uint32_t*)&h45; hp.w = *(uint32_t*)&h67;
            lp.x = *(uint32_t*)&l01; lp.y = *(uint32_t*)&l23;
            lp.z = *(uint32_t*)&l45; lp.w = *(uint32_t*)&l67;
            *reinterpret_cast<uint4*>(smem + S_AHI + soff) = hp;
            *reinterpret_cast<uint4*>(smem + S_ALO + soff) = lp;
        }
        asm volatile("cp.async.wait_group 0;" ::: "memory");
        __syncthreads();

#pragma unroll
        for (int ks = 0; ks < 4; ks++) {
            uint32_t ahi[2][4], alo[2][4];
#pragma unroll
            for (int ms = 0; ms < 2; ms++) {
                int r = wm + ms * 16 + (lane & 15);
                int c16 = ks * 2 + (lane >> 4);
                uint32_t off = (uint32_t)r * 128u + (uint32_t)(((c16 ^ (r & 7))) << 4);
                ldsm_x4(ahi[ms], sbase + S_AHI + off);
                ldsm_x4(alo[ms], sbase + S_ALO + off);
            }
#pragma unroll
            for (int p = 0; p < 4; p++) {
                int n = wn + p * 16 + ((lane >> 4) << 3) + (lane & 7);
                int c16 = ks * 2 + ((lane >> 3) & 1);
                uint32_t off = (uint32_t)n * 128u + (uint32_t)(((c16 ^ (n & 7))) << 4);
                uint32_t bh[4], bl[4];
                ldsm_x4(bh, sbase + S_BHI + off);
                ldsm_x4(bl, sbase + S_BLO + off);
#pragma unroll
                for (int ms = 0; ms < 2; ms++) {
                    mma16816(acc[ms][2 * p],     ahi[ms], bh[0], bh[1]);
                    mma16816(acc[ms][2 * p + 1], ahi[ms], bh[2], bh[3]);
                    mma16816(acc[ms][2 * p],     alo[ms], bh[0], bh[1]);
                    mma16816(acc[ms][2 * p + 1], alo[ms], bh[2], bh[3]);
                    mma16816(acc[ms][2 * p],     ahi[ms], bl[0], bl[1]);
                    mma16816(acc[ms][2 * p + 1], ahi[ms], bl[2], bl[3]);
                }
            }
        }
        __syncthreads();
    }

    // ---- epilogue ----
#pragma unroll
    for (int ms = 0; ms < 2; ms++) {
#pragma unroll
        for (int nt = 0; nt < 8; nt++) {
            int c = col0 + wn + nt * 8 + (lane & 3) * 2;
            float2 bi = *reinterpret_cast<const float2*>(bias + c);
            int r = row0 + wm + ms * 16 + (lane >> 2);
#pragma unroll
            for (int half = 0; half < 2; half++) {
                int rr = r + half * 8;
                if (rr >= M) continue;
                float2 v;
                v.x = acc[ms][nt][2 * half + 0] + bi.x;
                v.y = acc[ms][nt][2 * half + 1] + bi.y;
                if (EOP == 1) { v.x = fmaxf(v.x, 0.f); v.y = fmaxf(v.y, 0.f); }
                float* cp = C + (size_t)rr * Nw + c;
                if (EOP == 2) {
                    float2 o = *reinterpret_cast<const float2*>(cp);
                    v.x += o.x; v.y += o.y;
                }
                *reinterpret_cast<float2*>(cp) = v;
            }
        }
    }

    // ---- fused BN statistics (msg1 only) ----
    if (STATS) {
        float* ssum = reinterpret_cast<float*>(smem);        // 128 floats
        float* ssq  = reinterpret_cast<float*>(smem) + 128;  // 128 floats
        if (tid < 128) { ssum[tid] = 0.f; ssq[tid] = 0.f; }
        __syncthreads();
#pragma unroll
        for (int nt = 0; nt < 8; nt++) {
#pragma unroll
            for (int j = 0; j < 2; j++) {
                int cl = wn + nt * 8 + (lane & 3) * 2 + j;
                float bi = __ldg(bias + col0 + cl);
                float s = 0.f, q = 0.f;
#pragma unroll
                for (int ms = 0; ms < 2; ms++)
#pragma unroll
                    for (int half = 0; half < 2; half++) {
                        int rr = row0 + wm + ms * 16 + (lane >> 2) + half * 8;
                        float v = (rr < M) ? (acc[ms][nt][2 * half + j] + bi) : 0.f;
                        s += v; q += v * v;
                    }
                s += __shfl_down_sync(0xFFFFFFFFu, s, 16);
                s += __shfl_down_sync(0xFFFFFFFFu, s, 8);
                s += __shfl_down_sync(0xFFFFFFFFu, s, 4);
                q += __shfl_down_sync(0xFFFFFFFFu, q, 16);
                q += __shfl_down_sync(0xFFFFFFFFu, q, 8);
                q += __shfl_down_sync(0xFFFFFFFFu, q, 4);
                if ((lane >> 2) == 0) {
                    atomicAdd(&ssum[cl], s);
                    atomicAdd(&ssq[cl], q);
                }
            }
        }
        __syncthreads();
        if (tid < 128) {
            atomicAdd(&g_sum[col0 + tid], ssum[tid]);
            atomicAdd(&g_sumsq[col0 + tid], ssq[tid]);
        }
    }
}

// ---------------- host orchestration ---------------------------------------
extern "C" void kernel_launch(void* const* d_in, const int* in_sizes, int n_in,
                              void* d_out, int out_size) {
    const float* x_in    = (const float*)d_in[0];
    const int*   edge    = (const int*)d_in[1];
    const int*   se0     = (const int*)d_in[2];
    const int*   se1     = (const int*)d_in[3];
    const float* msg_w1  = (const float*)d_in[4];
    const float* msg_b1  = (const float*)d_in[5];
    const float* bn_g    = (const float*)d_in[6];
    const float* bn_b    = (const float*)d_in[7];
    const float* msg_w2  = (const float*)d_in[8];
    const float* msg_b2  = (const float*)d_in[9];
    const float* eps_gin = (const float*)d_in[10];
    const float* n2s_w1  = (const float*)d_in[11];
    const float* n2s_b1  = (const float*)d_in[12];
    const float* n2s_w2  = (const float*)d_in[13];
    const float* n2s_b2  = (const float*)d_in[14];
    const float* s2n_w1  = (const float*)d_in[15];
    const float* s2n_b1  = (const float*)d_in[16];
    const float* s2n_w2  = (const float*)d_in[17];
    const float* s2n_b2  = (const float*)d_in[18];
    const float* out_w1  = (const float*)d_in[19];
    const float* out_b1  = (const float*)d_in[20];
    const float* out_w2  = (const float*)d_in[21];
    const float* out_b2  = (const float*)d_in[22];

    float *xb, *aggb, *hb, *msgb, *sxb, *sxhb, *sx2b, *scaleb, *shiftb;
    __nv_bfloat16 *whi, *wlo;
    int *cnt2, *cursor2, *offsb, *partb, *csrb;
    cudaGetSymbolAddress((void**)&xb,    g_x);
    cudaGetSymbolAddress((void**)&aggb,  g_agg);
    cudaGetSymbolAddress((void**)&hb,    g_h);
    cudaGetSymbolAddress((void**)&msgb,  g_msg);
    cudaGetSymbolAddress((void**)&sxb,   g_sx);
    cudaGetSymbolAddress((void**)&sxhb,  g_sxh);
    cudaGetSymbolAddress((void**)&sx2b,  g_sx2);
    cudaGetSymbolAddress((void**)&scaleb, g_scale);
    cudaGetSymbolAddress((void**)&shiftb, g_shift);
    cudaGetSymbolAddress((void**)&whi,   g_whi);
    cudaGetSymbolAddress((void**)&wlo,   g_wlo);
    cudaGetSymbolAddress((void**)&cnt2,    g_cnt2);
    cudaGetSymbolAddress((void**)&cursor2, g_cursor2);
    cudaGetSymbolAddress((void**)&offsb,   g_offs);
    cudaGetSymbolAddress((void**)&partb,   g_part);
    cudaGetSymbolAddress((void**)&csrb,    g_csr);

    cudaFuncSetAttribute(k_gemm_mma<0, 0, 1>, cudaFuncAttributeMaxDynamicSharedMemorySize, GEMM_SMEM);
    cudaFuncSetAttribute(k_gemm_mma<0, 0, 0>, cudaFuncAttributeMaxDynamicSharedMemorySize, GEMM_SMEM);
    cudaFuncSetAttribute(k_gemm_mma<1, 0, 0>, cudaFuncAttributeMaxDynamicSharedMemorySize, GEMM_SMEM);
    cudaFuncSetAttribute(k_gemm_mma<0, 1, 0>, cudaFuncAttributeMaxDynamicSharedMemorySize, GEMM_SMEM);
    cudaFuncSetAttribute(k_gemm_mma<0, 2, 0>, cudaFuncAttributeMaxDynamicSharedMemorySize, GEMM_SMEM);

    const size_t O_MSG1 = 0,       O_MSG2 = 98304,  O_N2S1 = 196608, O_N2S2 = 393216;
    const size_t O_S2N1 = 589824,  O_S2N2 = 786432, O_OUT1 = 983040, O_OUT2 = 1015808;

    const int gGN = (N_NODES + 7) / 8;
    const int gGS = (NSUB + 7) / 8;
    const int EB = (CSR_E + 255) / 256;

    // launches 0-4: CSR build; 5: GIN gather (ncu -s 5 target)
    k_hist_all<<<EB, 256>>>(edge, se0, se1, cnt2);
    k_scanA<<<NBLK_SCAN, 1024>>>(cnt2, offsb, partb);
    k_scanB<<<1, 1024>>>(partb);
    k_scanC<<<NBLK_SCAN, 1024>>>(offsb, partb, cursor2);
    k_fill_all<<<EB, 256>>>(edge, se0, se1, cursor2, csrb);
    k_gather<1><<<gGN, 256>>>(aggb, x_in, offsb, csrb, x_in, eps_gin, 0, N_NODES);
    k_zeroi<<<(CSR_R + 255) / 256, 256>>>(cnt2, CSR_R);  // restore counts-zero invariant
    k_zero_stats<<<1, 256>>>();                           // BN accumulators start at 0
    k_prep_all<<<(W_TOTAL + 255) / 256, 256>>>(msg_w1, msg_w2, n2s_w1, n2s_w2,
                                               s2n_w1, s2n_w2, out_w1, out_w2, whi, wlo);

    dim3 gN2(2, (N_NODES + 127) / 128);
    dim3 gN1(1, (N_NODES + 127) / 128);
    dim3 gS2(2, (NSUB + 127) / 128);
    dim3 gS1(1, (NSUB + 127) / 128);

    for (int i = 0; i < NLAYERS; i++) {
        if (i > 0)
            k_gather<1><<<gGN, 256>>>(aggb, xb, offsb, csrb, xb, eps_gin, i, N_NODES);

        // h = agg @ msg_w1 + b1, with fused column stats
        k_gemm_mma<0, 0, 1><<<gN2, 256, GEMM_SMEM>>>(
            aggb, whi + O_MSG1 + (size_t)i * HDIM * H2DIM, wlo + O_MSG1 + (size_t)i * HDIM * H2DIM,
            msg_b1 + (size_t)i * H2DIM, hb, N_NODES, HDIM, H2DIM, nullptr, nullptr);
        k_bnfin<<<1, 256>>>(bn_g + (size_t)i * H2DIM, bn_b + (size_t)i * H2DIM,
                            1.0f / (float)N_NODES);
        k_gemm_mma<1, 0, 0><<<gN1, 256, GEMM_SMEM>>>(
            hb, whi + O_MSG2 + (size_t)i * H2DIM * HDIM, wlo + O_MSG2 + (size_t)i * H2DIM * HDIM,
            msg_b2 + (size_t)i * HDIM, xb, N_NODES, H2DIM, HDIM, scaleb, shiftb);

        for (int s = 0; s < NSUBT; s++) {
            const int* offc = offsb + ((s == 0) ? B_S0C : B_S1C);
            const int* offr = offsb + ((s == 0) ? B_S0R : B_S1R);
            const size_t widx = (size_t)i * NSUBT + s;

            k_gather<0><<<gGS, 256>>>(sxb, xb, offc, csrb, nullptr, nullptr, 0, NSUB);

            k_gemm_mma<0, 1, 0><<<gS2, 256, GEMM_SMEM>>>(
                sxb, whi + O_N2S1 + widx * HDIM * H2DIM, wlo + O_N2S1 + widx * HDIM * H2DIM,
                n2s_b1 + widx * H2DIM, sxhb, NSUB, HDIM, H2DIM, nullptr, nullptr);
            k_gemm_mma<0, 0, 0><<<gS1, 256, GEMM_SMEM>>>(
                sxhb, whi + O_N2S2 + widx * H2DIM * HDIM, wlo + O_N2S2 + widx * H2DIM * HDIM,
                n2s_b2 + widx * HDIM, sx2b, NSUB, H2DIM, HDIM, nullptr, nullptr);

            k_gather<0><<<gGN, 256>>>(msgb, sx2b, offr, csrb, nullptr, nullptr, 0, N_NODES);

            k_gemm_mma<0, 1, 0><<<gN2, 256, GEMM_SMEM>>>(
                msgb, whi + O_S2N1 + widx * HDIM * H2DIM, wlo + O_S2N1 + widx * HDIM * H2DIM,
                s2n_b1 + widx * H2DIM, hb, N_NODES, HDIM, H2DIM, nullptr, nullptr);
            k_gemm_mma<0, 2, 0><<<gN1, 256, GEMM_SMEM>>>(
                hb, whi + O_S2N2 + widx * H2DIM * HDIM, wlo + O_S2N2 + widx * H2DIM * HDIM,
                s2n_b2 + widx * HDIM, xb, N_NODES, H2DIM, HDIM, nullptr, nullptr);
        }
    }

    k_gemm_mma<0, 1, 0><<<gN2, 256, GEMM_SMEM>>>(
        xb, whi + O_OUT1, wlo + O_OUT1, out_b1, hb, N_NODES, HDIM, H2DIM, nullptr, nullptr);
    k_gemm_mma<0, 0, 0><<<gN1, 256, GEMM_SMEM>>>(
        hb, whi + O_OUT2, wlo + O_OUT2, out_b2, (float*)d_out,
        N_NODES, H2DIM, OUTDIM, nullptr, nullptr);
}